// round 2
// baseline (speedup 1.0000x reference)
#include <cuda_runtime.h>
#include <math.h>
#include <float.h>

#define SLEN 2048
#define HID  4096
#define NQH  32
#define NKVH 8
#define HDIM 128
#define QKVN 6144   // (32 + 2*8) * 128
#define EPSV 1e-6f

// Scratch (allocation-free rule: __device__ globals)
__device__ float g_qkv[(size_t)SLEN * QKVN];                 // 50 MB
__device__ float g_scores[(size_t)NQH * SLEN * SLEN];        // 537 MB
__device__ float g_attn[(size_t)SLEN * HID];                 // 34 MB

// ---------------------------------------------------------------------------
// Generic 128x128x8 SGEMM, 256 threads, 8x8 microtile with split row/col
// mapping (rows {tr*4..+3, 64+tr*4..+3}, cols likewise) for conflict-free
// float4 LDS in the inner loop.
//   NT        : C = A * B^T (B stored row-major [N,K]) — used for Q@K^T
//   MASKSCALE : epilogue applies *scale and causal mask (col>row -> -inf);
//               fully-masked tiles short-circuit to a -inf fill
//   CAUSALK   : K-loop clamped to row0+BM (A is lower-triangular-ish) — P@V
// Batch (blockIdx.z): A += z*aStride, B += (z/bDiv)*bStride, C += z*cStride
// ---------------------------------------------------------------------------
template<bool NT, bool MASKSCALE, bool CAUSALK>
__global__ __launch_bounds__(256) void sgemm(
    const float* __restrict__ Abase, int lda, long aStride,
    const float* __restrict__ Bbase, int ldb, long bStride, int bDiv,
    float* __restrict__ Cbase, int ldc, long cStride,
    int M, int N, int K, float scale)
{
    constexpr int BM = 128, BN = 128, BK = 8;
    __shared__ float As[BK][BM];
    __shared__ float Bs[BK][BN];

    const int z = blockIdx.z;
    const float* A = Abase + (long)z * aStride;
    const float* B = Bbase + (long)(z / bDiv) * bStride;
    float* C = Cbase + (long)z * cStride;

    const int row0 = blockIdx.y * BM;
    const int col0 = blockIdx.x * BN;
    const int tid = threadIdx.x;
    const int tr = tid >> 4;   // 0..15
    const int tc = tid & 15;   // 0..15

    if (MASKSCALE) {
        // Block entirely above the diagonal: pure -inf fill, no compute.
        if (col0 > row0 + BM - 1) {
            const float4 ninf = make_float4(-INFINITY, -INFINITY, -INFINITY, -INFINITY);
            #pragma unroll
            for (int i = 0; i < 8; i++) {
                int r = row0 + ((i < 4) ? (tr * 4 + i) : (64 + tr * 4 + (i - 4)));
                *reinterpret_cast<float4*>(&C[(long)r * ldc + col0 + tc * 4]) = ninf;
                *reinterpret_cast<float4*>(&C[(long)r * ldc + col0 + 64 + tc * 4]) = ninf;
            }
            return;
        }
    }

    float acc[8][8];
    #pragma unroll
    for (int i = 0; i < 8; i++)
        #pragma unroll
        for (int j = 0; j < 8; j++)
            acc[i][j] = 0.f;

    int kEnd = K;
    if (CAUSALK) {
        int ke = row0 + BM;
        kEnd = (ke < K) ? ke : K;
    }

    for (int k0 = 0; k0 < kEnd; k0 += BK) {
        // --- load A tile (BMxBK) transposed into As[k][m] ---
        {
            int r = tid >> 1;
            int c = (tid & 1) * 4;
            float4 v = *reinterpret_cast<const float4*>(&A[(long)(row0 + r) * lda + k0 + c]);
            As[c + 0][r] = v.x; As[c + 1][r] = v.y; As[c + 2][r] = v.z; As[c + 3][r] = v.w;
        }
        // --- load B tile into Bs[k][n] ---
        if (!NT) {
            int r = tid >> 5;            // k row 0..7
            int c = (tid & 31) * 4;      // n col
            float4 v = *reinterpret_cast<const float4*>(&B[(long)(k0 + r) * ldb + col0 + c]);
            *reinterpret_cast<float4*>(&Bs[r][c]) = v;
        } else {
            int r = tid >> 1;            // n row 0..127
            int c = (tid & 1) * 4;       // k col
            float4 v = *reinterpret_cast<const float4*>(&B[(long)(col0 + r) * ldb + k0 + c]);
            Bs[c + 0][r] = v.x; Bs[c + 1][r] = v.y; Bs[c + 2][r] = v.z; Bs[c + 3][r] = v.w;
        }
        __syncthreads();

        #pragma unroll
        for (int kk = 0; kk < BK; kk++) {
            float a[8], b[8];
            float4 t;
            t = *reinterpret_cast<const float4*>(&As[kk][tr * 4]);
            a[0] = t.x; a[1] = t.y; a[2] = t.z; a[3] = t.w;
            t = *reinterpret_cast<const float4*>(&As[kk][64 + tr * 4]);
            a[4] = t.x; a[5] = t.y; a[6] = t.z; a[7] = t.w;
            t = *reinterpret_cast<const float4*>(&Bs[kk][tc * 4]);
            b[0] = t.x; b[1] = t.y; b[2] = t.z; b[3] = t.w;
            t = *reinterpret_cast<const float4*>(&Bs[kk][64 + tc * 4]);
            b[4] = t.x; b[5] = t.y; b[6] = t.z; b[7] = t.w;
            #pragma unroll
            for (int i = 0; i < 8; i++)
                #pragma unroll
                for (int j = 0; j < 8; j++)
                    acc[i][j] = fmaf(a[i], b[j], acc[i][j]);
        }
        __syncthreads();
    }

    // --- epilogue ---
    #pragma unroll
    for (int i = 0; i < 8; i++) {
        int r = row0 + ((i < 4) ? (tr * 4 + i) : (64 + tr * 4 + (i - 4)));
        #pragma unroll
        for (int half = 0; half < 2; half++) {
            float vals[4];
            #pragma unroll
            for (int j = 0; j < 4; j++) {
                float v = acc[i][half * 4 + j];
                if (MASKSCALE) {
                    int cidx = col0 + half * 64 + tc * 4 + j;
                    v = (cidx <= r) ? v * scale : -INFINITY;
                }
                vals[j] = v;
            }
            float4 o = make_float4(vals[0], vals[1], vals[2], vals[3]);
            *reinterpret_cast<float4*>(&C[(long)r * ldc + col0 + half * 64 + tc * 4]) = o;
        }
    }
}

// ---------------------------------------------------------------------------
// Fused RMSNorm (per head over HD=128) + RoPE, in place on g_qkv.
// Grid: (SLEN, NQH+NKVH), 128 threads.
// ---------------------------------------------------------------------------
__global__ __launch_bounds__(128) void rmsnorm_rope(
    const float* __restrict__ cosT, const float* __restrict__ sinT,
    const float* __restrict__ q_gamma, const float* __restrict__ k_gamma)
{
    const int s = blockIdx.x;
    const int h = blockIdx.y;           // 0..39
    float* x;
    const float* gamma;
    if (h < NQH) { x = g_qkv + (size_t)s * QKVN + h * HDIM;              gamma = q_gamma; }
    else         { x = g_qkv + (size_t)s * QKVN + NQH * HDIM + (h - NQH) * HDIM; gamma = k_gamma; }

    const int tid = threadIdx.x;        // 0..127
    float v = x[tid];
    float sq = v * v;
    #pragma unroll
    for (int o = 16; o > 0; o >>= 1) sq += __shfl_xor_sync(0xffffffffu, sq, o);
    __shared__ float ws[4];
    if ((tid & 31) == 0) ws[tid >> 5] = sq;
    __syncthreads();
    float total = ws[0] + ws[1] + ws[2] + ws[3];
    float rinv = rsqrtf(total * (1.0f / HDIM) + EPSV);

    __shared__ float xn[HDIM];
    xn[tid] = v * rinv * gamma[tid];
    __syncthreads();

    if (tid < 64) {
        float c = cosT[(size_t)s * 64 + tid];
        float sn = sinT[(size_t)s * 64 + tid];
        float x1 = xn[tid];
        float x2 = xn[tid + 64];
        x[tid]      = x1 * c - x2 * sn;
        x[tid + 64] = x2 * c + x1 * sn;
    }
}

// ---------------------------------------------------------------------------
// Row softmax over SLEN (masked entries hold -inf -> exp()=0).
// Grid: (SLEN rows, NQH heads), 256 threads.
// ---------------------------------------------------------------------------
__global__ __launch_bounds__(256) void softmax_rows(float* __restrict__ scores)
{
    float* p = scores + ((size_t)blockIdx.y * SLEN + blockIdx.x) * SLEN;
    const int tid = threadIdx.x;
    __shared__ float red[8];

    float m = -FLT_MAX;
    for (int j = tid; j < SLEN; j += 256) m = fmaxf(m, p[j]);
    #pragma unroll
    for (int o = 16; o > 0; o >>= 1) m = fmaxf(m, __shfl_xor_sync(0xffffffffu, m, o));
    if ((tid & 31) == 0) red[tid >> 5] = m;
    __syncthreads();
    if (tid < 32) {
        float mm = (tid < 8) ? red[tid] : -FLT_MAX;
        #pragma unroll
        for (int o = 4; o > 0; o >>= 1) mm = fmaxf(mm, __shfl_xor_sync(0xffffffffu, mm, o));
        if (tid == 0) red[0] = mm;
    }
    __syncthreads();
    m = red[0];
    __syncthreads();

    float s = 0.f;
    for (int j = tid; j < SLEN; j += 256) { float e = expf(p[j] - m); p[j] = e; s += e; }
    #pragma unroll
    for (int o = 16; o > 0; o >>= 1) s += __shfl_xor_sync(0xffffffffu, s, o);
    if ((tid & 31) == 0) red[tid >> 5] = s;
    __syncthreads();
    if (tid < 32) {
        float ss = (tid < 8) ? red[tid] : 0.f;
        #pragma unroll
        for (int o = 4; o > 0; o >>= 1) ss += __shfl_xor_sync(0xffffffffu, ss, o);
        if (tid == 0) red[0] = ss;
    }
    __syncthreads();
    float inv = 1.f / red[0];
    for (int j = tid; j < SLEN; j += 256) p[j] *= inv;
}

// ---------------------------------------------------------------------------
// Inputs (metadata order): positions, hidden_states, Wqkv, Wo, q_gamma,
// k_gamma, cos, sin. Output: [2048, 4096] fp32.
// ---------------------------------------------------------------------------
extern "C" void kernel_launch(void* const* d_in, const int* in_sizes, int n_in,
                              void* d_out, int out_size)
{
    (void)in_sizes; (void)n_in; (void)out_size;
    const float* hidden = (const float*)d_in[1];
    const float* Wqkv   = (const float*)d_in[2];
    const float* Wo     = (const float*)d_in[3];
    const float* qg     = (const float*)d_in[4];
    const float* kg     = (const float*)d_in[5];
    const float* cosT   = (const float*)d_in[6];
    const float* sinT   = (const float*)d_in[7];
    float* out = (float*)d_out;

    float *qkv, *scores, *attn;
    cudaGetSymbolAddress((void**)&qkv, g_qkv);
    cudaGetSymbolAddress((void**)&scores, g_scores);
    cudaGetSymbolAddress((void**)&attn, g_attn);

    // 1) QKV projection: [2048,4096] @ [4096,6144]
    sgemm<false, false, false><<<dim3(QKVN / 128, SLEN / 128, 1), 256>>>(
        hidden, HID, 0, Wqkv, QKVN, 0, 1, qkv, QKVN, 0, SLEN, QKVN, HID, 1.f);

    // 2) RMSNorm + RoPE in place on Q and K heads
    rmsnorm_rope<<<dim3(SLEN, NQH + NKVH), 128>>>(cosT, sinT, qg, kg);

    // 3) Scores = Q @ K^T * HD^-0.5 with causal mask (per head, GQA z/4)
    sgemm<true, true, false><<<dim3(SLEN / 128, SLEN / 128, NQH), 256>>>(
        qkv, QKVN, HDIM,
        qkv + NQH * HDIM, QKVN, HDIM, 4,
        scores, SLEN, (long)SLEN * SLEN,
        SLEN, SLEN, HDIM, 0.08838834764831845f);

    // 4) Row softmax
    softmax_rows<<<dim3(SLEN, NQH), 256>>>(scores);

    // 5) attn = P @ V (causal K clamp), written into [2048, 32*128] layout
    sgemm<false, false, true><<<dim3(1, SLEN / 128, NQH), 256>>>(
        scores, SLEN, (long)SLEN * SLEN,
        qkv + (NQH + NKVH) * HDIM, QKVN, HDIM, 4,
        attn, HID, HDIM,
        SLEN, HDIM, SLEN, 1.f);

    // 6) Output projection: [2048,4096] @ [4096,4096]
    sgemm<false, false, false><<<dim3(HID / 128, SLEN / 128, 1), 256>>>(
        attn, HID, 0, Wo, HID, 0, 1, out, HID, 0, SLEN, HID, HID, 1.f);
}

// round 8
// speedup vs baseline: 1.7191x; 1.7191x over previous
#include <cuda_runtime.h>
#include <cuda_bf16.h>
#include <math.h>
#include <float.h>
#include <stdint.h>

#define SLEN 2048
#define HID  4096
#define NQH  32
#define NKVH 8
#define HDIM 128
#define QKVN 6144   // (32 + 2*8) * 128
#define EPSV 1e-6f

// ---------------- scratch (__device__ globals; no allocation) ---------------
__device__ float g_qkv[(size_t)SLEN * QKVN];                 // 50 MB
__device__ float g_scores[(size_t)NQH * SLEN * SLEN];        // 537 MB
__device__ float g_attn[(size_t)SLEN * HID];                 // 34 MB
__device__ __nv_bfloat16 g_wT_hi[(size_t)QKVN * HID];        // 50 MB
__device__ __nv_bfloat16 g_wT_lo[(size_t)QKVN * HID];        // 50 MB
__device__ __nv_bfloat16 g_a_hi[(size_t)SLEN * HID];         // 16 MB
__device__ __nv_bfloat16 g_a_lo[(size_t)SLEN * HID];         // 16 MB

// ---------------- helpers ----------------------------------------------------
__device__ __forceinline__ uint32_t smem_to_u32(const void* p) {
    uint32_t a;
    asm("{ .reg .u64 t; cvta.to.shared.u64 t, %1; cvt.u32.u64 %0, t; }" : "=r"(a) : "l"(p));
    return a;
}
__device__ __forceinline__ void cp16(uint32_t dst, const void* src) {
    asm volatile("cp.async.cg.shared.global [%0], [%1], 16;" :: "r"(dst), "l"(src));
}
__device__ __forceinline__ uint32_t lds32(uint32_t addr) {
    uint32_t v;
    asm volatile("ld.shared.b32 %0, [%1];" : "=r"(v) : "r"(addr));
    return v;
}
__device__ __forceinline__ void mma16816(float* c, const uint32_t* a, const uint32_t* b) {
    asm volatile(
        "mma.sync.aligned.m16n8k16.row.col.f32.bf16.bf16.f32 "
        "{%0,%1,%2,%3}, {%4,%5,%6,%7}, {%8,%9}, {%0,%1,%2,%3};"
        : "+f"(c[0]), "+f"(c[1]), "+f"(c[2]), "+f"(c[3])
        : "r"(a[0]), "r"(a[1]), "r"(a[2]), "r"(a[3]), "r"(b[0]), "r"(b[1]));
}

// ---------------------------------------------------------------------------
// mma.sync bf16x3 GEMM: C[M,N] = A[M,K] * Bt[N,K]^T, fp32 accumulate.
// CTA 128x128, 8 warps (4x2), warp tile 32x64 (2x8 m16n8k16 atoms).
// K chunk 64, SMEM rows padded to 72 bf16 (conflict-free fragment LDS),
// cp.async double-buffered.
// ---------------------------------------------------------------------------
#define MM_KC 64
#define MM_LDK 72                              // bf16 elements per padded row
#define MM_ROWB (MM_LDK * 2)                   // 144 bytes per row
#define MM_TILE_BYTES (128 * MM_ROWB)          // 18432
#define MM_STAGE (4 * MM_TILE_BYTES)           // 73728 (Ahi,Alo,Bhi,Blo)
#define MM_SMEM_TOT (2 * MM_STAGE)             // 147456

__global__ __launch_bounds__(256, 1) void gemm_mma_bf16x3(
    const __nv_bfloat16* __restrict__ Ahi, const __nv_bfloat16* __restrict__ Alo,
    const __nv_bfloat16* __restrict__ Bthi, const __nv_bfloat16* __restrict__ Btlo,
    float* __restrict__ C, int K, int N)
{
    extern __shared__ char smem[];
    const uint32_t sbase = smem_to_u32(smem);
    const int tid = threadIdx.x;
    const int wid = tid >> 5, lane = tid & 31;
    const int wm = wid >> 1, wn = wid & 1;          // 4x2 warp grid
    const int row0 = blockIdx.y * 128;
    const int n0 = blockIdx.x * 128;
    const int gq = lane >> 2;                       // 0..7  (group)
    const int tq = lane & 3;                        // 0..3  (thread-in-group)

    float acc[2][8][4];
    #pragma unroll
    for (int mt = 0; mt < 2; mt++)
        #pragma unroll
        for (int nt = 0; nt < 8; nt++)
            #pragma unroll
            for (int i = 0; i < 4; i++)
                acc[mt][nt][i] = 0.f;

    const int NCH = K / MM_KC;

    // ---- stage fill via cp.async (16 x 16B per thread) ----
    auto fill = [&](int s, int c) {
        const uint32_t sb = sbase + s * MM_STAGE;
        const int k0 = c * MM_KC;
        #pragma unroll
        for (int i = 0; i < 4; i++) {
            int idx = i * 256 + tid;
            int r = idx >> 3;            // 0..127
            int seg = idx & 7;           // 8B-bf16 segment (16 bytes)
            uint32_t dst = sb + r * MM_ROWB + seg * 16;
            size_t ao = (size_t)(row0 + r) * K + k0 + seg * 8;
            size_t bo = (size_t)(n0 + r) * K + k0 + seg * 8;
            cp16(dst,                      Ahi + ao);
            cp16(dst + MM_TILE_BYTES,      Alo + ao);
            cp16(dst + 2 * MM_TILE_BYTES,  Bthi + bo);
            cp16(dst + 3 * MM_TILE_BYTES,  Btlo + bo);
        }
        asm volatile("cp.async.commit_group;");
    };

    fill(0, 0);

    for (int c = 0; c < NCH; c++) {
        if (c + 1 < NCH) {
            fill((c + 1) & 1, c + 1);
            asm volatile("cp.async.wait_group 1;");
        } else {
            asm volatile("cp.async.wait_group 0;");
        }
        __syncthreads();

        const uint32_t sb = sbase + (c & 1) * MM_STAGE;
        #pragma unroll
        for (int ks = 0; ks < MM_KC / 16; ks++) {
            // A fragments (hi and lo) for both m-tiles
            uint32_t ah[2][4], al[2][4];
            #pragma unroll
            for (int mt = 0; mt < 2; mt++) {
                uint32_t base = sb + (wm * 32 + mt * 16 + gq) * MM_ROWB
                              + (ks * 16 + tq * 2) * 2;
                ah[mt][0] = lds32(base);
                ah[mt][1] = lds32(base + 8 * MM_ROWB);
                ah[mt][2] = lds32(base + 16);
                ah[mt][3] = lds32(base + 8 * MM_ROWB + 16);
                al[mt][0] = lds32(base + MM_TILE_BYTES);
                al[mt][1] = lds32(base + MM_TILE_BYTES + 8 * MM_ROWB);
                al[mt][2] = lds32(base + MM_TILE_BYTES + 16);
                al[mt][3] = lds32(base + MM_TILE_BYTES + 8 * MM_ROWB + 16);
            }
            #pragma unroll
            for (int nt = 0; nt < 8; nt++) {
                uint32_t bb = sb + 2 * MM_TILE_BYTES
                            + (wn * 64 + nt * 8 + gq) * MM_ROWB
                            + (ks * 16 + tq * 2) * 2;
                uint32_t bh[2], bl[2];
                bh[0] = lds32(bb);
                bh[1] = lds32(bb + 16);
                bl[0] = lds32(bb + MM_TILE_BYTES);
                bl[1] = lds32(bb + MM_TILE_BYTES + 16);
                #pragma unroll
                for (int mt = 0; mt < 2; mt++) {
                    mma16816(acc[mt][nt], ah[mt], bh);
                    mma16816(acc[mt][nt], ah[mt], bl);
                    mma16816(acc[mt][nt], al[mt], bh);
                }
            }
        }
        __syncthreads();
    }

    // ---- epilogue: float2 stores ----
    #pragma unroll
    for (int mt = 0; mt < 2; mt++) {
        int r = row0 + wm * 32 + mt * 16 + gq;
        #pragma unroll
        for (int nt = 0; nt < 8; nt++) {
            int cc = n0 + wn * 64 + nt * 8 + tq * 2;
            *reinterpret_cast<float2*>(&C[(size_t)r * N + cc]) =
                make_float2(acc[mt][nt][0], acc[mt][nt][1]);
            *reinterpret_cast<float2*>(&C[(size_t)(r + 8) * N + cc]) =
                make_float2(acc[mt][nt][2], acc[mt][nt][3]);
        }
    }
}

// ---------------------------------------------------------------------------
// fp32 -> bf16 hi/lo split (elementwise)
// ---------------------------------------------------------------------------
__global__ void split_rows_kernel(const float* __restrict__ X,
                                  __nv_bfloat16* __restrict__ H,
                                  __nv_bfloat16* __restrict__ L, int n)
{
    int i = blockIdx.x * blockDim.x + threadIdx.x;
    if (i < n) {
        float x = X[i];
        __nv_bfloat16 h = __float2bfloat16(x);
        H[i] = h;
        L[i] = __float2bfloat16(x - __bfloat162float(h));
    }
}

// fp32 [K,N] -> transposed bf16 hi/lo [N,K]
__global__ __launch_bounds__(256) void split_transpose_kernel(
    const float* __restrict__ W, __nv_bfloat16* __restrict__ TH,
    __nv_bfloat16* __restrict__ TL, int K, int N)
{
    __shared__ float t[32][33];
    const int n0 = blockIdx.x * 32, k0 = blockIdx.y * 32;
    const int tx = threadIdx.x & 31, ty = threadIdx.x >> 5;
    #pragma unroll
    for (int i = 0; i < 4; i++)
        t[ty + 8 * i][tx] = W[(size_t)(k0 + ty + 8 * i) * N + n0 + tx];
    __syncthreads();
    #pragma unroll
    for (int i = 0; i < 4; i++) {
        float x = t[tx][ty + 8 * i];
        __nv_bfloat16 h = __float2bfloat16(x);
        size_t o = (size_t)(n0 + ty + 8 * i) * K + k0 + tx;
        TH[o] = h;
        TL[o] = __float2bfloat16(x - __bfloat162float(h));
    }
}

// ---------------------------------------------------------------------------
// SIMT SGEMM for attention path (unchanged)
// ---------------------------------------------------------------------------
template<bool NT, bool MASKSCALE, bool CAUSALK>
__global__ __launch_bounds__(256) void sgemm(
    const float* __restrict__ Abase, int lda, long aStride,
    const float* __restrict__ Bbase, int ldb, long bStride, int bDiv,
    float* __restrict__ Cbase, int ldc, long cStride,
    int M, int N, int K, float scale)
{
    constexpr int BM = 128, BN = 128, BK = 8;
    __shared__ float As[BK][BM];
    __shared__ float Bs[BK][BN];

    const int z = blockIdx.z;
    const float* A = Abase + (long)z * aStride;
    const float* B = Bbase + (long)(z / bDiv) * bStride;
    float* C = Cbase + (long)z * cStride;

    const int row0 = blockIdx.y * BM;
    const int col0 = blockIdx.x * BN;
    const int tid = threadIdx.x;
    const int tr = tid >> 4;
    const int tc = tid & 15;

    if (MASKSCALE) {
        if (col0 > row0 + BM - 1) {
            const float4 ninf = make_float4(-INFINITY, -INFINITY, -INFINITY, -INFINITY);
            #pragma unroll
            for (int i = 0; i < 8; i++) {
                int r = row0 + ((i < 4) ? (tr * 4 + i) : (64 + tr * 4 + (i - 4)));
                *reinterpret_cast<float4*>(&C[(long)r * ldc + col0 + tc * 4]) = ninf;
                *reinterpret_cast<float4*>(&C[(long)r * ldc + col0 + 64 + tc * 4]) = ninf;
            }
            return;
        }
    }

    float acc[8][8];
    #pragma unroll
    for (int i = 0; i < 8; i++)
        #pragma unroll
        for (int j = 0; j < 8; j++)
            acc[i][j] = 0.f;

    int kEnd = K;
    if (CAUSALK) {
        int ke = row0 + BM;
        kEnd = (ke < K) ? ke : K;
    }

    for (int k0 = 0; k0 < kEnd; k0 += BK) {
        {
            int r = tid >> 1;
            int c = (tid & 1) * 4;
            float4 v = *reinterpret_cast<const float4*>(&A[(long)(row0 + r) * lda + k0 + c]);
            As[c + 0][r] = v.x; As[c + 1][r] = v.y; As[c + 2][r] = v.z; As[c + 3][r] = v.w;
        }
        if (!NT) {
            int r = tid >> 5;
            int c = (tid & 31) * 4;
            float4 v = *reinterpret_cast<const float4*>(&B[(long)(k0 + r) * ldb + col0 + c]);
            *reinterpret_cast<float4*>(&Bs[r][c]) = v;
        } else {
            int r = tid >> 1;
            int c = (tid & 1) * 4;
            float4 v = *reinterpret_cast<const float4*>(&B[(long)(col0 + r) * ldb + k0 + c]);
            Bs[c + 0][r] = v.x; Bs[c + 1][r] = v.y; Bs[c + 2][r] = v.z; Bs[c + 3][r] = v.w;
        }
        __syncthreads();

        #pragma unroll
        for (int kk = 0; kk < BK; kk++) {
            float a[8], b[8];
            float4 t;
            t = *reinterpret_cast<const float4*>(&As[kk][tr * 4]);
            a[0] = t.x; a[1] = t.y; a[2] = t.z; a[3] = t.w;
            t = *reinterpret_cast<const float4*>(&As[kk][64 + tr * 4]);
            a[4] = t.x; a[5] = t.y; a[6] = t.z; a[7] = t.w;
            t = *reinterpret_cast<const float4*>(&Bs[kk][tc * 4]);
            b[0] = t.x; b[1] = t.y; b[2] = t.z; b[3] = t.w;
            t = *reinterpret_cast<const float4*>(&Bs[kk][64 + tc * 4]);
            b[4] = t.x; b[5] = t.y; b[6] = t.z; b[7] = t.w;
            #pragma unroll
            for (int i = 0; i < 8; i++)
                #pragma unroll
                for (int j = 0; j < 8; j++)
                    acc[i][j] = fmaf(a[i], b[j], acc[i][j]);
        }
        __syncthreads();
    }

    #pragma unroll
    for (int i = 0; i < 8; i++) {
        int r = row0 + ((i < 4) ? (tr * 4 + i) : (64 + tr * 4 + (i - 4)));
        #pragma unroll
        for (int half = 0; half < 2; half++) {
            float vals[4];
            #pragma unroll
            for (int j = 0; j < 4; j++) {
                float v = acc[i][half * 4 + j];
                if (MASKSCALE) {
                    int cidx = col0 + half * 64 + tc * 4 + j;
                    v = (cidx <= r) ? v * scale : -INFINITY;
                }
                vals[j] = v;
            }
            float4 o = make_float4(vals[0], vals[1], vals[2], vals[3]);
            *reinterpret_cast<float4*>(&C[(long)r * ldc + col0 + half * 64 + tc * 4]) = o;
        }
    }
}

// ---------------------------------------------------------------------------
// RMSNorm + RoPE (unchanged)
// ---------------------------------------------------------------------------
__global__ __launch_bounds__(128) void rmsnorm_rope(
    const float* __restrict__ cosT, const float* __restrict__ sinT,
    const float* __restrict__ q_gamma, const float* __restrict__ k_gamma)
{
    const int s = blockIdx.x;
    const int h = blockIdx.y;
    float* x;
    const float* gamma;
    if (h < NQH) { x = g_qkv + (size_t)s * QKVN + h * HDIM;                        gamma = q_gamma; }
    else         { x = g_qkv + (size_t)s * QKVN + NQH * HDIM + (h - NQH) * HDIM;  gamma = k_gamma; }

    const int tid = threadIdx.x;
    float v = x[tid];
    float sq = v * v;
    #pragma unroll
    for (int o = 16; o > 0; o >>= 1) sq += __shfl_xor_sync(0xffffffffu, sq, o);
    __shared__ float ws[4];
    if ((tid & 31) == 0) ws[tid >> 5] = sq;
    __syncthreads();
    float total = ws[0] + ws[1] + ws[2] + ws[3];
    float rinv = rsqrtf(total * (1.0f / HDIM) + EPSV);

    __shared__ float xn[HDIM];
    xn[tid] = v * rinv * gamma[tid];
    __syncthreads();

    if (tid < 64) {
        float c = cosT[(size_t)s * 64 + tid];
        float sn = sinT[(size_t)s * 64 + tid];
        float x1 = xn[tid];
        float x2 = xn[tid + 64];
        x[tid]      = x1 * c - x2 * sn;
        x[tid + 64] = x2 * c + x1 * sn;
    }
}

// ---------------------------------------------------------------------------
// Row softmax (unchanged)
// ---------------------------------------------------------------------------
__global__ __launch_bounds__(256) void softmax_rows(float* __restrict__ scores)
{
    float* p = scores + ((size_t)blockIdx.y * SLEN + blockIdx.x) * SLEN;
    const int tid = threadIdx.x;
    __shared__ float red[8];

    float m = -FLT_MAX;
    for (int j = tid; j < SLEN; j += 256) m = fmaxf(m, p[j]);
    #pragma unroll
    for (int o = 16; o > 0; o >>= 1) m = fmaxf(m, __shfl_xor_sync(0xffffffffu, m, o));
    if ((tid & 31) == 0) red[tid >> 5] = m;
    __syncthreads();
    if (tid < 32) {
        float mm = (tid < 8) ? red[tid] : -FLT_MAX;
        #pragma unroll
        for (int o = 4; o > 0; o >>= 1) mm = fmaxf(mm, __shfl_xor_sync(0xffffffffu, mm, o));
        if (tid == 0) red[0] = mm;
    }
    __syncthreads();
    m = red[0];
    __syncthreads();

    float s = 0.f;
    for (int j = tid; j < SLEN; j += 256) { float e = expf(p[j] - m); p[j] = e; s += e; }
    #pragma unroll
    for (int o = 16; o > 0; o >>= 1) s += __shfl_xor_sync(0xffffffffu, s, o);
    if ((tid & 31) == 0) red[tid >> 5] = s;
    __syncthreads();
    if (tid < 32) {
        float ss = (tid < 8) ? red[tid] : 0.f;
        #pragma unroll
        for (int o = 4; o > 0; o >>= 1) ss += __shfl_xor_sync(0xffffffffu, ss, o);
        if (tid == 0) red[0] = ss;
    }
    __syncthreads();
    float inv = 1.f / red[0];
    for (int j = tid; j < SLEN; j += 256) p[j] *= inv;
}

// ---------------------------------------------------------------------------
// launch
// ---------------------------------------------------------------------------
extern "C" void kernel_launch(void* const* d_in, const int* in_sizes, int n_in,
                              void* d_out, int out_size)
{
    (void)in_sizes; (void)n_in; (void)out_size;
    const float* hidden = (const float*)d_in[1];
    const float* Wqkv   = (const float*)d_in[2];
    const float* Wo     = (const float*)d_in[3];
    const float* qg     = (const float*)d_in[4];
    const float* kg     = (const float*)d_in[5];
    const float* cosT   = (const float*)d_in[6];
    const float* sinT   = (const float*)d_in[7];
    float* out = (float*)d_out;

    float *qkv, *scores, *attn;
    __nv_bfloat16 *wT_hi, *wT_lo, *a_hi, *a_lo;
    cudaGetSymbolAddress((void**)&qkv, g_qkv);
    cudaGetSymbolAddress((void**)&scores, g_scores);
    cudaGetSymbolAddress((void**)&attn, g_attn);
    cudaGetSymbolAddress((void**)&wT_hi, g_wT_hi);
    cudaGetSymbolAddress((void**)&wT_lo, g_wT_lo);
    cudaGetSymbolAddress((void**)&a_hi, g_a_hi);
    cudaGetSymbolAddress((void**)&a_lo, g_a_lo);

    cudaFuncSetAttribute(gemm_mma_bf16x3, cudaFuncAttributeMaxDynamicSharedMemorySize, MM_SMEM_TOT);

    // 1) QKV projection on HMMA (bf16x3)
    split_transpose_kernel<<<dim3(QKVN / 32, HID / 32), 256>>>(Wqkv, wT_hi, wT_lo, HID, QKVN);
    split_rows_kernel<<<(SLEN * HID + 255) / 256, 256>>>(hidden, a_hi, a_lo, SLEN * HID);
    gemm_mma_bf16x3<<<dim3(QKVN / 128, SLEN / 128), 256, MM_SMEM_TOT>>>(
        a_hi, a_lo, wT_hi, wT_lo, qkv, HID, QKVN);

    // 2) RMSNorm + RoPE
    rmsnorm_rope<<<dim3(SLEN, NQH + NKVH), 128>>>(cosT, sinT, qg, kg);

    // 3) Scores = Q @ K^T * HD^-0.5 with causal mask
    sgemm<true, true, false><<<dim3(SLEN / 128, SLEN / 128, NQH), 256>>>(
        qkv, QKVN, HDIM,
        qkv + NQH * HDIM, QKVN, HDIM, 4,
        scores, SLEN, (long)SLEN * SLEN,
        SLEN, SLEN, HDIM, 0.08838834764831845f);

    // 4) Row softmax
    softmax_rows<<<dim3(SLEN, NQH), 256>>>(scores);

    // 5) attn = P @ V
    sgemm<false, false, true><<<dim3(1, SLEN / 128, NQH), 256>>>(
        scores, SLEN, (long)SLEN * SLEN,
        qkv + (NQH + NKVH) * HDIM, QKVN, HDIM, 4,
        attn, HID, HDIM,
        SLEN, HDIM, SLEN, 1.f);

    // 6) Output projection on HMMA (bf16x3)
    split_transpose_kernel<<<dim3(HID / 32, HID / 32), 256>>>(Wo, wT_hi, wT_lo, HID, HID);
    split_rows_kernel<<<(SLEN * HID + 255) / 256, 256>>>(attn, a_hi, a_lo, SLEN * HID);
    gemm_mma_bf16x3<<<dim3(HID / 128, SLEN / 128), 256, MM_SMEM_TOT>>>(
        a_hi, a_lo, wT_hi, wT_lo, out, HID, HID);
}

// round 12
// speedup vs baseline: 2.5391x; 1.4770x over previous
#include <cuda_runtime.h>
#include <cuda_bf16.h>
#include <math.h>
#include <float.h>
#include <stdint.h>

#define SLEN 2048
#define HID  4096
#define NQH  32
#define NKVH 8
#define HDIM 128
#define QKVN 6144   // (32 + 2*8) * 128
#define EPSV 1e-6f
#define QBLK 128
#define NQB  (SLEN / QBLK)     // 16
#define SCALE 0.08838834764831845f
#define L2E   1.44269504088896f

// ---------------- scratch (__device__ globals; no allocation) ---------------
__device__ float g_qkv[(size_t)SLEN * QKVN];                 // 50 MB
__device__ __nv_bfloat16 g_wT_hi[(size_t)QKVN * HID];        // 50 MB
__device__ __nv_bfloat16 g_wT_lo[(size_t)QKVN * HID];        // 50 MB
__device__ __nv_bfloat16 g_a_hi[(size_t)SLEN * HID];         // 16 MB
__device__ __nv_bfloat16 g_a_lo[(size_t)SLEN * HID];         // 16 MB
__device__ __nv_bfloat16 g_q_hi[(size_t)SLEN * NQH * HDIM];  // 16 MB
__device__ __nv_bfloat16 g_q_lo[(size_t)SLEN * NQH * HDIM];  // 16 MB
__device__ __nv_bfloat16 g_k_hi[(size_t)SLEN * NKVH * HDIM]; // 4 MB
__device__ __nv_bfloat16 g_k_lo[(size_t)SLEN * NKVH * HDIM]; // 4 MB
__device__ __nv_bfloat16 g_vt_hi[(size_t)NKVH * HDIM * SLEN];// 4 MB
__device__ __nv_bfloat16 g_vt_lo[(size_t)NKVH * HDIM * SLEN];// 4 MB

// ---------------- helpers ----------------------------------------------------
__device__ __forceinline__ uint32_t smem_to_u32(const void* p) {
    uint32_t a;
    asm("{ .reg .u64 t; cvta.to.shared.u64 t, %1; cvt.u32.u64 %0, t; }" : "=r"(a) : "l"(p));
    return a;
}
__device__ __forceinline__ void cp16(uint32_t dst, const void* src) {
    asm volatile("cp.async.cg.shared.global [%0], [%1], 16;" :: "r"(dst), "l"(src));
}
__device__ __forceinline__ uint32_t lds32(uint32_t addr) {
    uint32_t v;
    asm volatile("ld.shared.b32 %0, [%1];" : "=r"(v) : "r"(addr));
    return v;
}
__device__ __forceinline__ void mma16816(float* c, const uint32_t* a, const uint32_t* b) {
    asm volatile(
        "mma.sync.aligned.m16n8k16.row.col.f32.bf16.bf16.f32 "
        "{%0,%1,%2,%3}, {%4,%5,%6,%7}, {%8,%9}, {%0,%1,%2,%3};"
        : "+f"(c[0]), "+f"(c[1]), "+f"(c[2]), "+f"(c[3])
        : "r"(a[0]), "r"(a[1]), "r"(a[2]), "r"(a[3]), "r"(b[0]), "r"(b[1]));
}
__device__ __forceinline__ uint32_t packbf2(float a, float b) {
    __nv_bfloat162 h = __float22bfloat162_rn(make_float2(a, b));
    return *reinterpret_cast<uint32_t*>(&h);
}

// ---------------------------------------------------------------------------
// mma.sync bf16x3 GEMM (unchanged, R8-verified): C[M,N] = A[M,K] * Bt[N,K]^T
// ---------------------------------------------------------------------------
#define MM_KC 64
#define MM_LDK 72
#define MM_ROWB (MM_LDK * 2)
#define MM_TILE_BYTES (128 * MM_ROWB)
#define MM_STAGE (4 * MM_TILE_BYTES)
#define MM_SMEM_TOT (2 * MM_STAGE)

__global__ __launch_bounds__(256, 1) void gemm_mma_bf16x3(
    const __nv_bfloat16* __restrict__ Ahi, const __nv_bfloat16* __restrict__ Alo,
    const __nv_bfloat16* __restrict__ Bthi, const __nv_bfloat16* __restrict__ Btlo,
    float* __restrict__ C, int K, int N)
{
    extern __shared__ char smem[];
    const uint32_t sbase = smem_to_u32(smem);
    const int tid = threadIdx.x;
    const int wid = tid >> 5, lane = tid & 31;
    const int wm = wid >> 1, wn = wid & 1;
    const int row0 = blockIdx.y * 128;
    const int n0 = blockIdx.x * 128;
    const int gq = lane >> 2;
    const int tq = lane & 3;

    float acc[2][8][4];
    #pragma unroll
    for (int mt = 0; mt < 2; mt++)
        #pragma unroll
        for (int nt = 0; nt < 8; nt++)
            #pragma unroll
            for (int i = 0; i < 4; i++)
                acc[mt][nt][i] = 0.f;

    const int NCH = K / MM_KC;

    auto fill = [&](int s, int c) {
        const uint32_t sb = sbase + s * MM_STAGE;
        const int k0 = c * MM_KC;
        #pragma unroll
        for (int i = 0; i < 4; i++) {
            int idx = i * 256 + tid;
            int r = idx >> 3;
            int seg = idx & 7;
            uint32_t dst = sb + r * MM_ROWB + seg * 16;
            size_t ao = (size_t)(row0 + r) * K + k0 + seg * 8;
            size_t bo = (size_t)(n0 + r) * K + k0 + seg * 8;
            cp16(dst,                      Ahi + ao);
            cp16(dst + MM_TILE_BYTES,      Alo + ao);
            cp16(dst + 2 * MM_TILE_BYTES,  Bthi + bo);
            cp16(dst + 3 * MM_TILE_BYTES,  Btlo + bo);
        }
        asm volatile("cp.async.commit_group;");
    };

    fill(0, 0);

    for (int c = 0; c < NCH; c++) {
        if (c + 1 < NCH) {
            fill((c + 1) & 1, c + 1);
            asm volatile("cp.async.wait_group 1;");
        } else {
            asm volatile("cp.async.wait_group 0;");
        }
        __syncthreads();

        const uint32_t sb = sbase + (c & 1) * MM_STAGE;
        #pragma unroll
        for (int ks = 0; ks < MM_KC / 16; ks++) {
            uint32_t ah[2][4], al[2][4];
            #pragma unroll
            for (int mt = 0; mt < 2; mt++) {
                uint32_t base = sb + (wm * 32 + mt * 16 + gq) * MM_ROWB
                              + (ks * 16 + tq * 2) * 2;
                ah[mt][0] = lds32(base);
                ah[mt][1] = lds32(base + 8 * MM_ROWB);
                ah[mt][2] = lds32(base + 16);
                ah[mt][3] = lds32(base + 8 * MM_ROWB + 16);
                al[mt][0] = lds32(base + MM_TILE_BYTES);
                al[mt][1] = lds32(base + MM_TILE_BYTES + 8 * MM_ROWB);
                al[mt][2] = lds32(base + MM_TILE_BYTES + 16);
                al[mt][3] = lds32(base + MM_TILE_BYTES + 8 * MM_ROWB + 16);
            }
            #pragma unroll
            for (int nt = 0; nt < 8; nt++) {
                uint32_t bb = sb + 2 * MM_TILE_BYTES
                            + (wn * 64 + nt * 8 + gq) * MM_ROWB
                            + (ks * 16 + tq * 2) * 2;
                uint32_t bh[2], bl[2];
                bh[0] = lds32(bb);
                bh[1] = lds32(bb + 16);
                bl[0] = lds32(bb + MM_TILE_BYTES);
                bl[1] = lds32(bb + MM_TILE_BYTES + 16);
                #pragma unroll
                for (int mt = 0; mt < 2; mt++) {
                    mma16816(acc[mt][nt], ah[mt], bh);
                    mma16816(acc[mt][nt], ah[mt], bl);
                    mma16816(acc[mt][nt], al[mt], bh);
                }
            }
        }
        __syncthreads();
    }

    #pragma unroll
    for (int mt = 0; mt < 2; mt++) {
        int r = row0 + wm * 32 + mt * 16 + gq;
        #pragma unroll
        for (int nt = 0; nt < 8; nt++) {
            int cc = n0 + wn * 64 + nt * 8 + tq * 2;
            *reinterpret_cast<float2*>(&C[(size_t)r * N + cc]) =
                make_float2(acc[mt][nt][0], acc[mt][nt][1]);
            *reinterpret_cast<float2*>(&C[(size_t)(r + 8) * N + cc]) =
                make_float2(acc[mt][nt][2], acc[mt][nt][3]);
        }
    }
}

// ---------------------------------------------------------------------------
// Fused flash attention on HMMA.
// R12: P also split hi/lo (3-MMA P*V) to push P-quantization error ~1e-5.
// Grid (NQB, NQH), 256 threads (8 warps x 16 query rows).
// ---------------------------------------------------------------------------
#define FA_ROWB 272
#define FA_TILE (128 * FA_ROWB)     // 34816
#define FA_QHI  0
#define FA_QLO  (1 * FA_TILE)
#define FA_KHI  (2 * FA_TILE)
#define FA_KLO  (3 * FA_TILE)
#define FA_VHI  (4 * FA_TILE)
#define FA_VLO  (5 * FA_TILE)
#define FA_SMEM (6 * FA_TILE)       // 208896

__global__ __launch_bounds__(256, 1) void flash_attn(
    const __nv_bfloat16* __restrict__ qhi, const __nv_bfloat16* __restrict__ qlo,
    const __nv_bfloat16* __restrict__ khi, const __nv_bfloat16* __restrict__ klo,
    const __nv_bfloat16* __restrict__ vthi, const __nv_bfloat16* __restrict__ vtlo,
    __nv_bfloat16* __restrict__ outhi, __nv_bfloat16* __restrict__ outlo)
{
    extern __shared__ char smem[];
    const uint32_t sb = smem_to_u32(smem);
    const int tid = threadIdx.x;
    const int wid = tid >> 5, lane = tid & 31;
    const int gq = lane >> 2, tq = lane & 3;
    const int qb = (NQB - 1) - blockIdx.x;       // long blocks first
    const int h = blockIdx.y;
    const int kh = h >> 2;                       // GQA: 4 q-heads per kv-head
    const int r0 = qb * QBLK;
    const int wrow = wid * 16;

    // ---- Q tile load (once), fully waited before use ----
    {
        const __nv_bfloat16* srcH = qhi + ((size_t)r0 * NQH + h) * HDIM;
        const __nv_bfloat16* srcL = qlo + ((size_t)r0 * NQH + h) * HDIM;
        #pragma unroll
        for (int i = 0; i < 8; i++) {
            int idx = i * 256 + tid;
            int r = idx >> 4, seg = idx & 15;          // 128 rows x 16 segs
            size_t so = (size_t)r * (NQH * HDIM) + seg * 8;
            uint32_t dst = sb + r * FA_ROWB + seg * 16;
            cp16(dst + FA_QHI, srcH + so);
            cp16(dst + FA_QLO, srcL + so);
        }
        asm volatile("cp.async.commit_group;");
        asm volatile("cp.async.wait_group 0;");
    }
    __syncthreads();

    float m0 = -1e30f, m1 = -1e30f, l0 = 0.f, l1 = 0.f;
    float o[16][4];
    #pragma unroll
    for (int nt = 0; nt < 16; nt++)
        #pragma unroll
        for (int i = 0; i < 4; i++) o[nt][i] = 0.f;

    for (int j = 0; j <= qb; j++) {
        const int t0 = j * QBLK;
        // ---- K group, then V group ----
        {
            const __nv_bfloat16* srcH = khi + ((size_t)t0 * NKVH + kh) * HDIM;
            const __nv_bfloat16* srcL = klo + ((size_t)t0 * NKVH + kh) * HDIM;
            #pragma unroll
            for (int i = 0; i < 8; i++) {
                int idx = i * 256 + tid;
                int r = idx >> 4, seg = idx & 15;
                size_t so = (size_t)r * (NKVH * HDIM) + seg * 8;
                uint32_t dst = sb + r * FA_ROWB + seg * 16;
                cp16(dst + FA_KHI, srcH + so);
                cp16(dst + FA_KLO, srcL + so);
            }
            asm volatile("cp.async.commit_group;");
            const __nv_bfloat16* svH = vthi + (size_t)kh * HDIM * SLEN + t0;
            const __nv_bfloat16* svL = vtlo + (size_t)kh * HDIM * SLEN + t0;
            #pragma unroll
            for (int i = 0; i < 8; i++) {
                int idx = i * 256 + tid;
                int r = idx >> 4, seg = idx & 15;
                size_t so = (size_t)r * SLEN + seg * 8;
                uint32_t dst = sb + r * FA_ROWB + seg * 16;
                cp16(dst + FA_VHI, svH + so);
                cp16(dst + FA_VLO, svL + so);
            }
            asm volatile("cp.async.commit_group;");
        }
        asm volatile("cp.async.wait_group 1;");   // K ready; V may be in flight
        __syncthreads();

        // ---- S = Q K^T (bf16x3) ----
        float s[16][4];
        #pragma unroll
        for (int nt = 0; nt < 16; nt++)
            #pragma unroll
            for (int i = 0; i < 4; i++) s[nt][i] = 0.f;

        #pragma unroll
        for (int ks = 0; ks < 8; ks++) {
            uint32_t qoff = (uint32_t)((wrow + gq) * FA_ROWB + ks * 32 + tq * 4);
            uint32_t ah[4], al[4];
            ah[0] = lds32(sb + FA_QHI + qoff);
            ah[1] = lds32(sb + FA_QHI + qoff + 8 * FA_ROWB);
            ah[2] = lds32(sb + FA_QHI + qoff + 16);
            ah[3] = lds32(sb + FA_QHI + qoff + 8 * FA_ROWB + 16);
            al[0] = lds32(sb + FA_QLO + qoff);
            al[1] = lds32(sb + FA_QLO + qoff + 8 * FA_ROWB);
            al[2] = lds32(sb + FA_QLO + qoff + 16);
            al[3] = lds32(sb + FA_QLO + qoff + 8 * FA_ROWB + 16);
            #pragma unroll
            for (int nt = 0; nt < 16; nt++) {
                uint32_t koff = (uint32_t)((nt * 8 + gq) * FA_ROWB + ks * 32 + tq * 4);
                uint32_t bh[2], bl[2];
                bh[0] = lds32(sb + FA_KHI + koff);
                bh[1] = lds32(sb + FA_KHI + koff + 16);
                bl[0] = lds32(sb + FA_KLO + koff);
                bl[1] = lds32(sb + FA_KLO + koff + 16);
                mma16816(s[nt], ah, bh);
                mma16816(s[nt], ah, bl);
                mma16816(s[nt], al, bh);
            }
        }

        // ---- scale + causal mask (diagonal block only) ----
        #pragma unroll
        for (int nt = 0; nt < 16; nt++)
            #pragma unroll
            for (int i = 0; i < 4; i++) s[nt][i] *= SCALE;
        if (j == qb) {
            const int lr0 = wrow + gq, lr1 = lr0 + 8;
            #pragma unroll
            for (int nt = 0; nt < 16; nt++) {
                int c0 = nt * 8 + tq * 2;
                if (c0 > lr0)     s[nt][0] = -1e30f;
                if (c0 + 1 > lr0) s[nt][1] = -1e30f;
                if (c0 > lr1)     s[nt][2] = -1e30f;
                if (c0 + 1 > lr1) s[nt][3] = -1e30f;
            }
        }

        // ---- online softmax (quad-level row reductions) ----
        float rm0 = -1e30f, rm1 = -1e30f;
        #pragma unroll
        for (int nt = 0; nt < 16; nt++) {
            rm0 = fmaxf(rm0, fmaxf(s[nt][0], s[nt][1]));
            rm1 = fmaxf(rm1, fmaxf(s[nt][2], s[nt][3]));
        }
        rm0 = fmaxf(rm0, __shfl_xor_sync(0xffffffffu, rm0, 1));
        rm0 = fmaxf(rm0, __shfl_xor_sync(0xffffffffu, rm0, 2));
        rm1 = fmaxf(rm1, __shfl_xor_sync(0xffffffffu, rm1, 1));
        rm1 = fmaxf(rm1, __shfl_xor_sync(0xffffffffu, rm1, 2));
        float mn0 = fmaxf(m0, rm0), mn1 = fmaxf(m1, rm1);
        float al0 = exp2f((m0 - mn0) * L2E), al1 = exp2f((m1 - mn1) * L2E);

        // ---- P = exp(S - m), split hi/lo for 3-MMA PV ----
        float sum0 = 0.f, sum1 = 0.f;
        uint32_t pbh[16][2], pbl[16][2];
        #pragma unroll
        for (int nt = 0; nt < 16; nt++) {
            float p0 = exp2f((s[nt][0] - mn0) * L2E);
            float p1 = exp2f((s[nt][1] - mn0) * L2E);
            float p2 = exp2f((s[nt][2] - mn1) * L2E);
            float p3 = exp2f((s[nt][3] - mn1) * L2E);
            sum0 += p0 + p1;
            sum1 += p2 + p3;
            __nv_bfloat16 h0 = __float2bfloat16(p0), h1 = __float2bfloat16(p1);
            __nv_bfloat16 h2 = __float2bfloat16(p2), h3 = __float2bfloat16(p3);
            pbh[nt][0] = packbf2(__bfloat162float(h0), __bfloat162float(h1));
            pbh[nt][1] = packbf2(__bfloat162float(h2), __bfloat162float(h3));
            pbl[nt][0] = packbf2(p0 - __bfloat162float(h0), p1 - __bfloat162float(h1));
            pbl[nt][1] = packbf2(p2 - __bfloat162float(h2), p3 - __bfloat162float(h3));
        }
        sum0 += __shfl_xor_sync(0xffffffffu, sum0, 1);
        sum0 += __shfl_xor_sync(0xffffffffu, sum0, 2);
        sum1 += __shfl_xor_sync(0xffffffffu, sum1, 1);
        sum1 += __shfl_xor_sync(0xffffffffu, sum1, 2);
        l0 = l0 * al0 + sum0;
        l1 = l1 * al1 + sum1;
        m0 = mn0; m1 = mn1;
        #pragma unroll
        for (int nt = 0; nt < 16; nt++) {
            o[nt][0] *= al0; o[nt][1] *= al0;
            o[nt][2] *= al1; o[nt][3] *= al1;
        }

        // ---- O += Phi*Vhi + Phi*Vlo + Plo*Vhi ----
        asm volatile("cp.async.wait_group 0;");
        __syncthreads();
        #pragma unroll
        for (int kt = 0; kt < 8; kt++) {
            uint32_t ah2[4] = { pbh[2 * kt][0], pbh[2 * kt][1],
                                pbh[2 * kt + 1][0], pbh[2 * kt + 1][1] };
            uint32_t al2[4] = { pbl[2 * kt][0], pbl[2 * kt][1],
                                pbl[2 * kt + 1][0], pbl[2 * kt + 1][1] };
            #pragma unroll
            for (int nd = 0; nd < 16; nd++) {
                uint32_t voff = (uint32_t)((nd * 8 + gq) * FA_ROWB + kt * 32 + tq * 4);
                uint32_t bh[2], bl[2];
                bh[0] = lds32(sb + FA_VHI + voff);
                bh[1] = lds32(sb + FA_VHI + voff + 16);
                bl[0] = lds32(sb + FA_VLO + voff);
                bl[1] = lds32(sb + FA_VLO + voff + 16);
                mma16816(o[nd], ah2, bh);
                mma16816(o[nd], ah2, bl);
                mma16816(o[nd], al2, bh);
            }
        }
        __syncthreads();   // all K/V reads done before next iter overwrites
    }

    // ---- epilogue: normalize + split to bf16 hi/lo ----
    const float inv0 = 1.f / fmaxf(l0, 1e-20f);
    const float inv1 = 1.f / fmaxf(l1, 1e-20f);
    const int grow0 = r0 + wrow + gq, grow1 = grow0 + 8;
    #pragma unroll
    for (int nt = 0; nt < 16; nt++) {
        int c = h * HDIM + nt * 8 + tq * 2;
        float f0 = o[nt][0] * inv0, f1 = o[nt][1] * inv0;
        float f2 = o[nt][2] * inv1, f3 = o[nt][3] * inv1;
        __nv_bfloat16 h0 = __float2bfloat16(f0), h1 = __float2bfloat16(f1);
        __nv_bfloat16 h2 = __float2bfloat16(f2), h3 = __float2bfloat16(f3);
        __nv_bfloat16 e0 = __float2bfloat16(f0 - __bfloat162float(h0));
        __nv_bfloat16 e1 = __float2bfloat16(f1 - __bfloat162float(h1));
        __nv_bfloat16 e2 = __float2bfloat16(f2 - __bfloat162float(h2));
        __nv_bfloat16 e3 = __float2bfloat16(f3 - __bfloat162float(h3));
        *reinterpret_cast<__nv_bfloat162*>(&outhi[(size_t)grow0 * HID + c]) =
            __nv_bfloat162(h0, h1);
        *reinterpret_cast<__nv_bfloat162*>(&outlo[(size_t)grow0 * HID + c]) =
            __nv_bfloat162(e0, e1);
        *reinterpret_cast<__nv_bfloat162*>(&outhi[(size_t)grow1 * HID + c]) =
            __nv_bfloat162(h2, h3);
        *reinterpret_cast<__nv_bfloat162*>(&outlo[(size_t)grow1 * HID + c]) =
            __nv_bfloat162(e2, e3);
    }
}

// ---------------------------------------------------------------------------
// RMSNorm + RoPE, reading fp32 qkv, writing bf16 hi/lo Q and K buffers.
// ---------------------------------------------------------------------------
__global__ __launch_bounds__(128) void rmsnorm_rope_split(
    const float* __restrict__ cosT, const float* __restrict__ sinT,
    const float* __restrict__ q_gamma, const float* __restrict__ k_gamma,
    __nv_bfloat16* __restrict__ qhi, __nv_bfloat16* __restrict__ qlo,
    __nv_bfloat16* __restrict__ khi, __nv_bfloat16* __restrict__ klo)
{
    const int s = blockIdx.x;
    const int h = blockIdx.y;           // 0..39
    const float* x;
    const float* gamma;
    __nv_bfloat16 *dh, *dl;
    if (h < NQH) {
        x = g_qkv + (size_t)s * QKVN + h * HDIM;
        gamma = q_gamma;
        dh = qhi + ((size_t)s * NQH + h) * HDIM;
        dl = qlo + ((size_t)s * NQH + h) * HDIM;
    } else {
        x = g_qkv + (size_t)s * QKVN + NQH * HDIM + (h - NQH) * HDIM;
        gamma = k_gamma;
        dh = khi + ((size_t)s * NKVH + (h - NQH)) * HDIM;
        dl = klo + ((size_t)s * NKVH + (h - NQH)) * HDIM;
    }

    const int tid = threadIdx.x;
    float v = x[tid];
    float sq = v * v;
    #pragma unroll
    for (int o = 16; o > 0; o >>= 1) sq += __shfl_xor_sync(0xffffffffu, sq, o);
    __shared__ float ws[4];
    if ((tid & 31) == 0) ws[tid >> 5] = sq;
    __syncthreads();
    float total = ws[0] + ws[1] + ws[2] + ws[3];
    float rinv = rsqrtf(total * (1.0f / HDIM) + EPSV);

    __shared__ float xn[HDIM];
    xn[tid] = v * rinv * gamma[tid];
    __syncthreads();

    if (tid < 64) {
        float c = cosT[(size_t)s * 64 + tid];
        float sn = sinT[(size_t)s * 64 + tid];
        float x1 = xn[tid];
        float x2 = xn[tid + 64];
        float y1 = x1 * c - x2 * sn;
        float y2 = x2 * c + x1 * sn;
        __nv_bfloat16 h1 = __float2bfloat16(y1);
        __nv_bfloat16 h2 = __float2bfloat16(y2);
        dh[tid] = h1;
        dh[tid + 64] = h2;
        dl[tid] = __float2bfloat16(y1 - __bfloat162float(h1));
        dl[tid + 64] = __float2bfloat16(y2 - __bfloat162float(h2));
    }
}

// ---------------------------------------------------------------------------
// V: fp32 [seq][kvh*128 cols] -> transposed bf16 hi/lo [kvh][d][seq]
// ---------------------------------------------------------------------------
__global__ __launch_bounds__(256) void v_split_transpose(
    __nv_bfloat16* __restrict__ TH, __nv_bfloat16* __restrict__ TL)
{
    __shared__ float t[32][33];
    const int t0 = blockIdx.x * 32;
    const int d0 = blockIdx.y * 32;
    const int kh = blockIdx.z;
    const int tx = threadIdx.x & 31, ty = threadIdx.x >> 5;
    #pragma unroll
    for (int i = 0; i < 4; i++)
        t[ty + 8 * i][tx] =
            g_qkv[(size_t)(t0 + ty + 8 * i) * QKVN + (NQH + NKVH) * HDIM + kh * HDIM + d0 + tx];
    __syncthreads();
    #pragma unroll
    for (int i = 0; i < 4; i++) {
        float x = t[tx][ty + 8 * i];
        __nv_bfloat16 h = __float2bfloat16(x);
        size_t o = ((size_t)kh * HDIM + d0 + ty + 8 * i) * SLEN + t0 + tx;
        TH[o] = h;
        TL[o] = __float2bfloat16(x - __bfloat162float(h));
    }
}

// ---------------------------------------------------------------------------
// fp32 -> bf16 hi/lo split (elementwise)
// ---------------------------------------------------------------------------
__global__ void split_rows_kernel(const float* __restrict__ X,
                                  __nv_bfloat16* __restrict__ H,
                                  __nv_bfloat16* __restrict__ L, int n)
{
    int i = blockIdx.x * blockDim.x + threadIdx.x;
    if (i < n) {
        float x = X[i];
        __nv_bfloat16 h = __float2bfloat16(x);
        H[i] = h;
        L[i] = __float2bfloat16(x - __bfloat162float(h));
    }
}

// fp32 [K,N] -> transposed bf16 hi/lo [N,K]
__global__ __launch_bounds__(256) void split_transpose_kernel(
    const float* __restrict__ W, __nv_bfloat16* __restrict__ TH,
    __nv_bfloat16* __restrict__ TL, int K, int N)
{
    __shared__ float t[32][33];
    const int n0 = blockIdx.x * 32, k0 = blockIdx.y * 32;
    const int tx = threadIdx.x & 31, ty = threadIdx.x >> 5;
    #pragma unroll
    for (int i = 0; i < 4; i++)
        t[ty + 8 * i][tx] = W[(size_t)(k0 + ty + 8 * i) * N + n0 + tx];
    __syncthreads();
    #pragma unroll
    for (int i = 0; i < 4; i++) {
        float x = t[tx][ty + 8 * i];
        __nv_bfloat16 h = __float2bfloat16(x);
        size_t o = (size_t)(n0 + ty + 8 * i) * K + k0 + tx;
        TH[o] = h;
        TL[o] = __float2bfloat16(x - __bfloat162float(h));
    }
}

// ---------------------------------------------------------------------------
// launch
// ---------------------------------------------------------------------------
extern "C" void kernel_launch(void* const* d_in, const int* in_sizes, int n_in,
                              void* d_out, int out_size)
{
    (void)in_sizes; (void)n_in; (void)out_size;
    const float* hidden = (const float*)d_in[1];
    const float* Wqkv   = (const float*)d_in[2];
    const float* Wo     = (const float*)d_in[3];
    const float* qg     = (const float*)d_in[4];
    const float* kg     = (const float*)d_in[5];
    const float* cosT   = (const float*)d_in[6];
    const float* sinT   = (const float*)d_in[7];
    float* out = (float*)d_out;

    float* qkv;
    __nv_bfloat16 *wT_hi, *wT_lo, *a_hi, *a_lo;
    __nv_bfloat16 *q_hi, *q_lo, *k_hi, *k_lo, *vt_hi, *vt_lo;
    cudaGetSymbolAddress((void**)&qkv, g_qkv);
    cudaGetSymbolAddress((void**)&wT_hi, g_wT_hi);
    cudaGetSymbolAddress((void**)&wT_lo, g_wT_lo);
    cudaGetSymbolAddress((void**)&a_hi, g_a_hi);
    cudaGetSymbolAddress((void**)&a_lo, g_a_lo);
    cudaGetSymbolAddress((void**)&q_hi, g_q_hi);
    cudaGetSymbolAddress((void**)&q_lo, g_q_lo);
    cudaGetSymbolAddress((void**)&k_hi, g_k_hi);
    cudaGetSymbolAddress((void**)&k_lo, g_k_lo);
    cudaGetSymbolAddress((void**)&vt_hi, g_vt_hi);
    cudaGetSymbolAddress((void**)&vt_lo, g_vt_lo);

    cudaFuncSetAttribute(gemm_mma_bf16x3, cudaFuncAttributeMaxDynamicSharedMemorySize, MM_SMEM_TOT);
    cudaFuncSetAttribute(flash_attn, cudaFuncAttributeMaxDynamicSharedMemorySize, FA_SMEM);

    // 1) QKV projection on HMMA (bf16x3)
    split_transpose_kernel<<<dim3(QKVN / 32, HID / 32), 256>>>(Wqkv, wT_hi, wT_lo, HID, QKVN);
    split_rows_kernel<<<(SLEN * HID + 255) / 256, 256>>>(hidden, a_hi, a_lo, SLEN * HID);
    gemm_mma_bf16x3<<<dim3(QKVN / 128, SLEN / 128), 256, MM_SMEM_TOT>>>(
        a_hi, a_lo, wT_hi, wT_lo, qkv, HID, QKVN);

    // 2) RMSNorm + RoPE -> bf16 hi/lo Q, K ; V transpose+split
    rmsnorm_rope_split<<<dim3(SLEN, NQH + NKVH), 128>>>(cosT, sinT, qg, kg,
                                                        q_hi, q_lo, k_hi, k_lo);
    v_split_transpose<<<dim3(SLEN / 32, HDIM / 32, NKVH), 256>>>(vt_hi, vt_lo);

    // 3) Fused flash attention -> a_hi/a_lo (O-proj input)
    flash_attn<<<dim3(NQB, NQH), 256, FA_SMEM>>>(
        q_hi, q_lo, k_hi, k_lo, vt_hi, vt_lo, a_hi, a_lo);

    // 4) Output projection on HMMA (bf16x3)
    split_transpose_kernel<<<dim3(HID / 32, HID / 32), 256>>>(Wo, wT_hi, wT_lo, HID, HID);
    gemm_mma_bf16x3<<<dim3(HID / 128, SLEN / 128), 256, MM_SMEM_TOT>>>(
        a_hi, a_lo, wT_hi, wT_lo, out, HID, HID);
}

// round 13
// speedup vs baseline: 2.5921x; 1.0209x over previous
#include <cuda_runtime.h>
#include <cuda_bf16.h>
#include <math.h>
#include <float.h>
#include <stdint.h>

#define SLEN 2048
#define HID  4096
#define NQH  32
#define NKVH 8
#define HDIM 128
#define QKVN 6144   // (32 + 2*8) * 128
#define EPSV 1e-6f
#define QBLK 128
#define NQB  (SLEN / QBLK)     // 16
#define SCALE 0.08838834764831845f
#define L2E   1.44269504088896f

// ---------------- scratch (__device__ globals; no allocation) ---------------
__device__ float g_qkv[(size_t)SLEN * QKVN];                 // 50 MB
__device__ __nv_bfloat16 g_wT_hi[(size_t)QKVN * HID];        // 50 MB
__device__ __nv_bfloat16 g_wT_lo[(size_t)QKVN * HID];        // 50 MB
__device__ __nv_bfloat16 g_a_hi[(size_t)SLEN * HID];         // 16 MB
__device__ __nv_bfloat16 g_a_lo[(size_t)SLEN * HID];         // 16 MB
__device__ __nv_bfloat16 g_q_hi[(size_t)SLEN * NQH * HDIM];  // 16 MB
__device__ __nv_bfloat16 g_q_lo[(size_t)SLEN * NQH * HDIM];  // 16 MB
__device__ __nv_bfloat16 g_k_hi[(size_t)SLEN * NKVH * HDIM]; // 4 MB
__device__ __nv_bfloat16 g_k_lo[(size_t)SLEN * NKVH * HDIM]; // 4 MB
__device__ __nv_bfloat16 g_vt_hi[(size_t)NKVH * HDIM * SLEN];// 4 MB
__device__ __nv_bfloat16 g_vt_lo[(size_t)NKVH * HDIM * SLEN];// 4 MB

// ---------------- helpers ----------------------------------------------------
__device__ __forceinline__ uint32_t smem_to_u32(const void* p) {
    uint32_t a;
    asm("{ .reg .u64 t; cvta.to.shared.u64 t, %1; cvt.u32.u64 %0, t; }" : "=r"(a) : "l"(p));
    return a;
}
__device__ __forceinline__ void cp16(uint32_t dst, const void* src) {
    asm volatile("cp.async.cg.shared.global [%0], [%1], 16;" :: "r"(dst), "l"(src));
}
__device__ __forceinline__ void ldsm4(uint32_t& r0, uint32_t& r1, uint32_t& r2, uint32_t& r3,
                                      uint32_t addr) {
    asm volatile("ldmatrix.sync.aligned.m8n8.x4.shared.b16 {%0,%1,%2,%3}, [%4];"
        : "=r"(r0), "=r"(r1), "=r"(r2), "=r"(r3) : "r"(addr));
}
__device__ __forceinline__ void mma16816(float* c, const uint32_t* a, const uint32_t* b) {
    asm volatile(
        "mma.sync.aligned.m16n8k16.row.col.f32.bf16.bf16.f32 "
        "{%0,%1,%2,%3}, {%4,%5,%6,%7}, {%8,%9}, {%0,%1,%2,%3};"
        : "+f"(c[0]), "+f"(c[1]), "+f"(c[2]), "+f"(c[3])
        : "r"(a[0]), "r"(a[1]), "r"(a[2]), "r"(a[3]), "r"(b[0]), "r"(b[1]));
}
__device__ __forceinline__ uint32_t packbf2(float a, float b) {
    __nv_bfloat162 h = __float22bfloat162_rn(make_float2(a, b));
    return *reinterpret_cast<uint32_t*>(&h);
}

// ---------------------------------------------------------------------------
// mma.sync bf16x3 GEMM with ldmatrix fragment loads.
// C[M,N] = A[M,K] * Bt[N,K]^T. CTA 128x128, 8 warps (4x2), warp 32x64.
// ---------------------------------------------------------------------------
#define MM_KC 64
#define MM_LDK 72
#define MM_ROWB (MM_LDK * 2)
#define MM_TILE_BYTES (128 * MM_ROWB)
#define MM_STAGE (4 * MM_TILE_BYTES)
#define MM_SMEM_TOT (2 * MM_STAGE)

__global__ __launch_bounds__(256, 1) void gemm_mma_bf16x3(
    const __nv_bfloat16* __restrict__ Ahi, const __nv_bfloat16* __restrict__ Alo,
    const __nv_bfloat16* __restrict__ Bthi, const __nv_bfloat16* __restrict__ Btlo,
    float* __restrict__ C, int K, int N)
{
    extern __shared__ char smem[];
    const uint32_t sbase = smem_to_u32(smem);
    const int tid = threadIdx.x;
    const int wid = tid >> 5, lane = tid & 31;
    const int wm = wid >> 1, wn = wid & 1;
    const int row0 = blockIdx.y * 128;
    const int n0 = blockIdx.x * 128;
    const int gq = lane >> 2;
    const int tq = lane & 3;
    // ldmatrix lane-address components
    const int l7 = lane & 7, lb8 = (lane >> 3) & 1, lb16 = (lane >> 4) & 1;

    float acc[2][8][4];
    #pragma unroll
    for (int mt = 0; mt < 2; mt++)
        #pragma unroll
        for (int nt = 0; nt < 8; nt++)
            #pragma unroll
            for (int i = 0; i < 4; i++)
                acc[mt][nt][i] = 0.f;

    const int NCH = K / MM_KC;

    auto fill = [&](int s, int c) {
        const uint32_t sb = sbase + s * MM_STAGE;
        const int k0 = c * MM_KC;
        #pragma unroll
        for (int i = 0; i < 4; i++) {
            int idx = i * 256 + tid;
            int r = idx >> 3;
            int seg = idx & 7;
            uint32_t dst = sb + r * MM_ROWB + seg * 16;
            size_t ao = (size_t)(row0 + r) * K + k0 + seg * 8;
            size_t bo = (size_t)(n0 + r) * K + k0 + seg * 8;
            cp16(dst,                      Ahi + ao);
            cp16(dst + MM_TILE_BYTES,      Alo + ao);
            cp16(dst + 2 * MM_TILE_BYTES,  Bthi + bo);
            cp16(dst + 3 * MM_TILE_BYTES,  Btlo + bo);
        }
        asm volatile("cp.async.commit_group;");
    };

    fill(0, 0);

    for (int c = 0; c < NCH; c++) {
        if (c + 1 < NCH) {
            fill((c + 1) & 1, c + 1);
            asm volatile("cp.async.wait_group 1;");
        } else {
            asm volatile("cp.async.wait_group 0;");
        }
        __syncthreads();

        const uint32_t sb = sbase + (c & 1) * MM_STAGE;
        #pragma unroll
        for (int ks = 0; ks < MM_KC / 16; ks++) {
            uint32_t ah[2][4], al[2][4];
            #pragma unroll
            for (int mt = 0; mt < 2; mt++) {
                uint32_t aaddr = sb + (uint32_t)((wm * 32 + mt * 16 + l7 + lb8 * 8) * MM_ROWB
                               + ks * 32 + lb16 * 16);
                ldsm4(ah[mt][0], ah[mt][1], ah[mt][2], ah[mt][3], aaddr);
                ldsm4(al[mt][0], al[mt][1], al[mt][2], al[mt][3], aaddr + MM_TILE_BYTES);
            }
            #pragma unroll
            for (int t = 0; t < 4; t++) {
                uint32_t baddr = sb + 2 * MM_TILE_BYTES
                               + (uint32_t)((wn * 64 + t * 16 + lb16 * 8 + l7) * MM_ROWB
                               + ks * 32 + lb8 * 16);
                uint32_t bh[4], bl[4];
                ldsm4(bh[0], bh[1], bh[2], bh[3], baddr);
                ldsm4(bl[0], bl[1], bl[2], bl[3], baddr + MM_TILE_BYTES);
                #pragma unroll
                for (int mt = 0; mt < 2; mt++) {
                    mma16816(acc[mt][2 * t],     ah[mt], bh + 0);
                    mma16816(acc[mt][2 * t],     ah[mt], bl + 0);
                    mma16816(acc[mt][2 * t],     al[mt], bh + 0);
                    mma16816(acc[mt][2 * t + 1], ah[mt], bh + 2);
                    mma16816(acc[mt][2 * t + 1], ah[mt], bl + 2);
                    mma16816(acc[mt][2 * t + 1], al[mt], bh + 2);
                }
            }
        }
        __syncthreads();
    }

    #pragma unroll
    for (int mt = 0; mt < 2; mt++) {
        int r = row0 + wm * 32 + mt * 16 + gq;
        #pragma unroll
        for (int nt = 0; nt < 8; nt++) {
            int cc = n0 + wn * 64 + nt * 8 + tq * 2;
            *reinterpret_cast<float2*>(&C[(size_t)r * N + cc]) =
                make_float2(acc[mt][nt][0], acc[mt][nt][1]);
            *reinterpret_cast<float2*>(&C[(size_t)(r + 8) * N + cc]) =
                make_float2(acc[mt][nt][2], acc[mt][nt][3]);
        }
    }
}

// ---------------------------------------------------------------------------
// Fused flash attention on HMMA, ldmatrix fragment loads.
// Grid (NQB, NQH), 256 threads (8 warps x 16 query rows).
// ---------------------------------------------------------------------------
#define FA_ROWB 272
#define FA_TILE (128 * FA_ROWB)     // 34816
#define FA_QHI  0
#define FA_QLO  (1 * FA_TILE)
#define FA_KHI  (2 * FA_TILE)
#define FA_KLO  (3 * FA_TILE)
#define FA_VHI  (4 * FA_TILE)
#define FA_VLO  (5 * FA_TILE)
#define FA_SMEM (6 * FA_TILE)       // 208896

__global__ __launch_bounds__(256, 1) void flash_attn(
    const __nv_bfloat16* __restrict__ qhi, const __nv_bfloat16* __restrict__ qlo,
    const __nv_bfloat16* __restrict__ khi, const __nv_bfloat16* __restrict__ klo,
    const __nv_bfloat16* __restrict__ vthi, const __nv_bfloat16* __restrict__ vtlo,
    __nv_bfloat16* __restrict__ outhi, __nv_bfloat16* __restrict__ outlo)
{
    extern __shared__ char smem[];
    const uint32_t sb = smem_to_u32(smem);
    const int tid = threadIdx.x;
    const int wid = tid >> 5, lane = tid & 31;
    const int gq = lane >> 2, tq = lane & 3;
    const int l7 = lane & 7, lb8 = (lane >> 3) & 1, lb16 = (lane >> 4) & 1;
    const int qb = (NQB - 1) - blockIdx.x;       // long blocks first
    const int h = blockIdx.y;
    const int kh = h >> 2;                       // GQA: 4 q-heads per kv-head
    const int r0 = qb * QBLK;
    const int wrow = wid * 16;

    // ---- Q tile load (once), fully waited before use ----
    {
        const __nv_bfloat16* srcH = qhi + ((size_t)r0 * NQH + h) * HDIM;
        const __nv_bfloat16* srcL = qlo + ((size_t)r0 * NQH + h) * HDIM;
        #pragma unroll
        for (int i = 0; i < 8; i++) {
            int idx = i * 256 + tid;
            int r = idx >> 4, seg = idx & 15;          // 128 rows x 16 segs
            size_t so = (size_t)r * (NQH * HDIM) + seg * 8;
            uint32_t dst = sb + r * FA_ROWB + seg * 16;
            cp16(dst + FA_QHI, srcH + so);
            cp16(dst + FA_QLO, srcL + so);
        }
        asm volatile("cp.async.commit_group;");
        asm volatile("cp.async.wait_group 0;");
    }
    __syncthreads();

    float m0 = -1e30f, m1 = -1e30f, l0 = 0.f, l1 = 0.f;
    float o[16][4];
    #pragma unroll
    for (int nt = 0; nt < 16; nt++)
        #pragma unroll
        for (int i = 0; i < 4; i++) o[nt][i] = 0.f;

    for (int j = 0; j <= qb; j++) {
        const int t0 = j * QBLK;
        // ---- K group, then V group ----
        {
            const __nv_bfloat16* srcH = khi + ((size_t)t0 * NKVH + kh) * HDIM;
            const __nv_bfloat16* srcL = klo + ((size_t)t0 * NKVH + kh) * HDIM;
            #pragma unroll
            for (int i = 0; i < 8; i++) {
                int idx = i * 256 + tid;
                int r = idx >> 4, seg = idx & 15;
                size_t so = (size_t)r * (NKVH * HDIM) + seg * 8;
                uint32_t dst = sb + r * FA_ROWB + seg * 16;
                cp16(dst + FA_KHI, srcH + so);
                cp16(dst + FA_KLO, srcL + so);
            }
            asm volatile("cp.async.commit_group;");
            const __nv_bfloat16* svH = vthi + (size_t)kh * HDIM * SLEN + t0;
            const __nv_bfloat16* svL = vtlo + (size_t)kh * HDIM * SLEN + t0;
            #pragma unroll
            for (int i = 0; i < 8; i++) {
                int idx = i * 256 + tid;
                int r = idx >> 4, seg = idx & 15;
                size_t so = (size_t)r * SLEN + seg * 8;
                uint32_t dst = sb + r * FA_ROWB + seg * 16;
                cp16(dst + FA_VHI, svH + so);
                cp16(dst + FA_VLO, svL + so);
            }
            asm volatile("cp.async.commit_group;");
        }
        asm volatile("cp.async.wait_group 1;");   // K ready; V may be in flight
        __syncthreads();

        // ---- S = Q K^T (bf16x3) ----
        float s[16][4];
        #pragma unroll
        for (int nt = 0; nt < 16; nt++)
            #pragma unroll
            for (int i = 0; i < 4; i++) s[nt][i] = 0.f;

        #pragma unroll
        for (int ks = 0; ks < 8; ks++) {
            uint32_t aaddr = sb + FA_QHI
                           + (uint32_t)((wrow + l7 + lb8 * 8) * FA_ROWB + ks * 32 + lb16 * 16);
            uint32_t ah[4], al[4];
            ldsm4(ah[0], ah[1], ah[2], ah[3], aaddr);
            ldsm4(al[0], al[1], al[2], al[3], aaddr + FA_TILE);
            #pragma unroll
            for (int t = 0; t < 8; t++) {
                uint32_t kaddr = sb + FA_KHI
                               + (uint32_t)((t * 16 + lb16 * 8 + l7) * FA_ROWB + ks * 32 + lb8 * 16);
                uint32_t bh[4], bl[4];
                ldsm4(bh[0], bh[1], bh[2], bh[3], kaddr);
                ldsm4(bl[0], bl[1], bl[2], bl[3], kaddr + FA_TILE);
                mma16816(s[2 * t],     ah, bh + 0);
                mma16816(s[2 * t],     ah, bl + 0);
                mma16816(s[2 * t],     al, bh + 0);
                mma16816(s[2 * t + 1], ah, bh + 2);
                mma16816(s[2 * t + 1], ah, bl + 2);
                mma16816(s[2 * t + 1], al, bh + 2);
            }
        }

        // ---- scale + causal mask (diagonal block only) ----
        #pragma unroll
        for (int nt = 0; nt < 16; nt++)
            #pragma unroll
            for (int i = 0; i < 4; i++) s[nt][i] *= SCALE;
        if (j == qb) {
            const int lr0 = wrow + gq, lr1 = lr0 + 8;
            #pragma unroll
            for (int nt = 0; nt < 16; nt++) {
                int c0 = nt * 8 + tq * 2;
                if (c0 > lr0)     s[nt][0] = -1e30f;
                if (c0 + 1 > lr0) s[nt][1] = -1e30f;
                if (c0 > lr1)     s[nt][2] = -1e30f;
                if (c0 + 1 > lr1) s[nt][3] = -1e30f;
            }
        }

        // ---- online softmax (quad-level row reductions) ----
        float rm0 = -1e30f, rm1 = -1e30f;
        #pragma unroll
        for (int nt = 0; nt < 16; nt++) {
            rm0 = fmaxf(rm0, fmaxf(s[nt][0], s[nt][1]));
            rm1 = fmaxf(rm1, fmaxf(s[nt][2], s[nt][3]));
        }
        rm0 = fmaxf(rm0, __shfl_xor_sync(0xffffffffu, rm0, 1));
        rm0 = fmaxf(rm0, __shfl_xor_sync(0xffffffffu, rm0, 2));
        rm1 = fmaxf(rm1, __shfl_xor_sync(0xffffffffu, rm1, 1));
        rm1 = fmaxf(rm1, __shfl_xor_sync(0xffffffffu, rm1, 2));
        float mn0 = fmaxf(m0, rm0), mn1 = fmaxf(m1, rm1);
        float al0 = exp2f((m0 - mn0) * L2E), al1 = exp2f((m1 - mn1) * L2E);

        // ---- P = exp(S - m), split hi/lo for 3-MMA PV ----
        float sum0 = 0.f, sum1 = 0.f;
        uint32_t pbh[16][2], pbl[16][2];
        #pragma unroll
        for (int nt = 0; nt < 16; nt++) {
            float p0 = exp2f((s[nt][0] - mn0) * L2E);
            float p1 = exp2f((s[nt][1] - mn0) * L2E);
            float p2 = exp2f((s[nt][2] - mn1) * L2E);
            float p3 = exp2f((s[nt][3] - mn1) * L2E);
            sum0 += p0 + p1;
            sum1 += p2 + p3;
            __nv_bfloat16 h0 = __float2bfloat16(p0), h1 = __float2bfloat16(p1);
            __nv_bfloat16 h2 = __float2bfloat16(p2), h3 = __float2bfloat16(p3);
            pbh[nt][0] = packbf2(__bfloat162float(h0), __bfloat162float(h1));
            pbh[nt][1] = packbf2(__bfloat162float(h2), __bfloat162float(h3));
            pbl[nt][0] = packbf2(p0 - __bfloat162float(h0), p1 - __bfloat162float(h1));
            pbl[nt][1] = packbf2(p2 - __bfloat162float(h2), p3 - __bfloat162float(h3));
        }
        sum0 += __shfl_xor_sync(0xffffffffu, sum0, 1);
        sum0 += __shfl_xor_sync(0xffffffffu, sum0, 2);
        sum1 += __shfl_xor_sync(0xffffffffu, sum1, 1);
        sum1 += __shfl_xor_sync(0xffffffffu, sum1, 2);
        l0 = l0 * al0 + sum0;
        l1 = l1 * al1 + sum1;
        m0 = mn0; m1 = mn1;
        #pragma unroll
        for (int nt = 0; nt < 16; nt++) {
            o[nt][0] *= al0; o[nt][1] *= al0;
            o[nt][2] *= al1; o[nt][3] *= al1;
        }

        // ---- O += Phi*Vhi + Phi*Vlo + Plo*Vhi ----
        asm volatile("cp.async.wait_group 0;");
        __syncthreads();
        #pragma unroll
        for (int kt = 0; kt < 8; kt++) {
            uint32_t ah2[4] = { pbh[2 * kt][0], pbh[2 * kt][1],
                                pbh[2 * kt + 1][0], pbh[2 * kt + 1][1] };
            uint32_t al2[4] = { pbl[2 * kt][0], pbl[2 * kt][1],
                                pbl[2 * kt + 1][0], pbl[2 * kt + 1][1] };
            #pragma unroll
            for (int t = 0; t < 8; t++) {
                uint32_t vaddr = sb + FA_VHI
                               + (uint32_t)((t * 16 + lb16 * 8 + l7) * FA_ROWB + kt * 32 + lb8 * 16);
                uint32_t bh[4], bl[4];
                ldsm4(bh[0], bh[1], bh[2], bh[3], vaddr);
                ldsm4(bl[0], bl[1], bl[2], bl[3], vaddr + FA_TILE);
                mma16816(o[2 * t],     ah2, bh + 0);
                mma16816(o[2 * t],     ah2, bl + 0);
                mma16816(o[2 * t],     al2, bh + 0);
                mma16816(o[2 * t + 1], ah2, bh + 2);
                mma16816(o[2 * t + 1], ah2, bl + 2);
                mma16816(o[2 * t + 1], al2, bh + 2);
            }
        }
        __syncthreads();   // all K/V reads done before next iter overwrites
    }

    // ---- epilogue: normalize + split to bf16 hi/lo ----
    const float inv0 = 1.f / fmaxf(l0, 1e-20f);
    const float inv1 = 1.f / fmaxf(l1, 1e-20f);
    const int grow0 = r0 + wrow + gq, grow1 = grow0 + 8;
    #pragma unroll
    for (int nt = 0; nt < 16; nt++) {
        int c = h * HDIM + nt * 8 + tq * 2;
        float f0 = o[nt][0] * inv0, f1 = o[nt][1] * inv0;
        float f2 = o[nt][2] * inv1, f3 = o[nt][3] * inv1;
        __nv_bfloat16 h0 = __float2bfloat16(f0), h1 = __float2bfloat16(f1);
        __nv_bfloat16 h2 = __float2bfloat16(f2), h3 = __float2bfloat16(f3);
        __nv_bfloat16 e0 = __float2bfloat16(f0 - __bfloat162float(h0));
        __nv_bfloat16 e1 = __float2bfloat16(f1 - __bfloat162float(h1));
        __nv_bfloat16 e2 = __float2bfloat16(f2 - __bfloat162float(h2));
        __nv_bfloat16 e3 = __float2bfloat16(f3 - __bfloat162float(h3));
        *reinterpret_cast<__nv_bfloat162*>(&outhi[(size_t)grow0 * HID + c]) =
            __nv_bfloat162(h0, h1);
        *reinterpret_cast<__nv_bfloat162*>(&outlo[(size_t)grow0 * HID + c]) =
            __nv_bfloat162(e0, e1);
        *reinterpret_cast<__nv_bfloat162*>(&outhi[(size_t)grow1 * HID + c]) =
            __nv_bfloat162(h2, h3);
        *reinterpret_cast<__nv_bfloat162*>(&outlo[(size_t)grow1 * HID + c]) =
            __nv_bfloat162(e2, e3);
    }
}

// ---------------------------------------------------------------------------
// RMSNorm + RoPE, reading fp32 qkv, writing bf16 hi/lo Q and K buffers.
// ---------------------------------------------------------------------------
__global__ __launch_bounds__(128) void rmsnorm_rope_split(
    const float* __restrict__ cosT, const float* __restrict__ sinT,
    const float* __restrict__ q_gamma, const float* __restrict__ k_gamma,
    __nv_bfloat16* __restrict__ qhi, __nv_bfloat16* __restrict__ qlo,
    __nv_bfloat16* __restrict__ khi, __nv_bfloat16* __restrict__ klo)
{
    const int s = blockIdx.x;
    const int h = blockIdx.y;           // 0..39
    const float* x;
    const float* gamma;
    __nv_bfloat16 *dh, *dl;
    if (h < NQH) {
        x = g_qkv + (size_t)s * QKVN + h * HDIM;
        gamma = q_gamma;
        dh = qhi + ((size_t)s * NQH + h) * HDIM;
        dl = qlo + ((size_t)s * NQH + h) * HDIM;
    } else {
        x = g_qkv + (size_t)s * QKVN + NQH * HDIM + (h - NQH) * HDIM;
        gamma = k_gamma;
        dh = khi + ((size_t)s * NKVH + (h - NQH)) * HDIM;
        dl = klo + ((size_t)s * NKVH + (h - NQH)) * HDIM;
    }

    const int tid = threadIdx.x;
    float v = x[tid];
    float sq = v * v;
    #pragma unroll
    for (int o = 16; o > 0; o >>= 1) sq += __shfl_xor_sync(0xffffffffu, sq, o);
    __shared__ float ws[4];
    if ((tid & 31) == 0) ws[tid >> 5] = sq;
    __syncthreads();
    float total = ws[0] + ws[1] + ws[2] + ws[3];
    float rinv = rsqrtf(total * (1.0f / HDIM) + EPSV);

    __shared__ float xn[HDIM];
    xn[tid] = v * rinv * gamma[tid];
    __syncthreads();

    if (tid < 64) {
        float c = cosT[(size_t)s * 64 + tid];
        float sn = sinT[(size_t)s * 64 + tid];
        float x1 = xn[tid];
        float x2 = xn[tid + 64];
        float y1 = x1 * c - x2 * sn;
        float y2 = x2 * c + x1 * sn;
        __nv_bfloat16 h1 = __float2bfloat16(y1);
        __nv_bfloat16 h2 = __float2bfloat16(y2);
        dh[tid] = h1;
        dh[tid + 64] = h2;
        dl[tid] = __float2bfloat16(y1 - __bfloat162float(h1));
        dl[tid + 64] = __float2bfloat16(y2 - __bfloat162float(h2));
    }
}

// ---------------------------------------------------------------------------
// V: fp32 [seq][kvh*128 cols] -> transposed bf16 hi/lo [kvh][d][seq]
// ---------------------------------------------------------------------------
__global__ __launch_bounds__(256) void v_split_transpose(
    __nv_bfloat16* __restrict__ TH, __nv_bfloat16* __restrict__ TL)
{
    __shared__ float t[32][33];
    const int t0 = blockIdx.x * 32;
    const int d0 = blockIdx.y * 32;
    const int kh = blockIdx.z;
    const int tx = threadIdx.x & 31, ty = threadIdx.x >> 5;
    #pragma unroll
    for (int i = 0; i < 4; i++)
        t[ty + 8 * i][tx] =
            g_qkv[(size_t)(t0 + ty + 8 * i) * QKVN + (NQH + NKVH) * HDIM + kh * HDIM + d0 + tx];
    __syncthreads();
    #pragma unroll
    for (int i = 0; i < 4; i++) {
        float x = t[tx][ty + 8 * i];
        __nv_bfloat16 h = __float2bfloat16(x);
        size_t o = ((size_t)kh * HDIM + d0 + ty + 8 * i) * SLEN + t0 + tx;
        TH[o] = h;
        TL[o] = __float2bfloat16(x - __bfloat162float(h));
    }
}

// ---------------------------------------------------------------------------
// fp32 -> bf16 hi/lo split (elementwise)
// ---------------------------------------------------------------------------
__global__ void split_rows_kernel(const float* __restrict__ X,
                                  __nv_bfloat16* __restrict__ H,
                                  __nv_bfloat16* __restrict__ L, int n)
{
    int i = blockIdx.x * blockDim.x + threadIdx.x;
    if (i < n) {
        float x = X[i];
        __nv_bfloat16 h = __float2bfloat16(x);
        H[i] = h;
        L[i] = __float2bfloat16(x - __bfloat162float(h));
    }
}

// fp32 [K,N] -> transposed bf16 hi/lo [N,K]
__global__ __launch_bounds__(256) void split_transpose_kernel(
    const float* __restrict__ W, __nv_bfloat16* __restrict__ TH,
    __nv_bfloat16* __restrict__ TL, int K, int N)
{
    __shared__ float t[32][33];
    const int n0 = blockIdx.x * 32, k0 = blockIdx.y * 32;
    const int tx = threadIdx.x & 31, ty = threadIdx.x >> 5;
    #pragma unroll
    for (int i = 0; i < 4; i++)
        t[ty + 8 * i][tx] = W[(size_t)(k0 + ty + 8 * i) * N + n0 + tx];
    __syncthreads();
    #pragma unroll
    for (int i = 0; i < 4; i++) {
        float x = t[tx][ty + 8 * i];
        __nv_bfloat16 h = __float2bfloat16(x);
        size_t o = (size_t)(n0 + ty + 8 * i) * K + k0 + tx;
        TH[o] = h;
        TL[o] = __float2bfloat16(x - __bfloat162float(h));
    }
}

// ---------------------------------------------------------------------------
// launch
// ---------------------------------------------------------------------------
extern "C" void kernel_launch(void* const* d_in, const int* in_sizes, int n_in,
                              void* d_out, int out_size)
{
    (void)in_sizes; (void)n_in; (void)out_size;
    const float* hidden = (const float*)d_in[1];
    const float* Wqkv   = (const float*)d_in[2];
    const float* Wo     = (const float*)d_in[3];
    const float* qg     = (const float*)d_in[4];
    const float* kg     = (const float*)d_in[5];
    const float* cosT   = (const float*)d_in[6];
    const float* sinT   = (const float*)d_in[7];
    float* out = (float*)d_out;

    float* qkv;
    __nv_bfloat16 *wT_hi, *wT_lo, *a_hi, *a_lo;
    __nv_bfloat16 *q_hi, *q_lo, *k_hi, *k_lo, *vt_hi, *vt_lo;
    cudaGetSymbolAddress((void**)&qkv, g_qkv);
    cudaGetSymbolAddress((void**)&wT_hi, g_wT_hi);
    cudaGetSymbolAddress((void**)&wT_lo, g_wT_lo);
    cudaGetSymbolAddress((void**)&a_hi, g_a_hi);
    cudaGetSymbolAddress((void**)&a_lo, g_a_lo);
    cudaGetSymbolAddress((void**)&q_hi, g_q_hi);
    cudaGetSymbolAddress((void**)&q_lo, g_q_lo);
    cudaGetSymbolAddress((void**)&k_hi, g_k_hi);
    cudaGetSymbolAddress((void**)&k_lo, g_k_lo);
    cudaGetSymbolAddress((void**)&vt_hi, g_vt_hi);
    cudaGetSymbolAddress((void**)&vt_lo, g_vt_lo);

    cudaFuncSetAttribute(gemm_mma_bf16x3, cudaFuncAttributeMaxDynamicSharedMemorySize, MM_SMEM_TOT);
    cudaFuncSetAttribute(flash_attn, cudaFuncAttributeMaxDynamicSharedMemorySize, FA_SMEM);

    // 1) QKV projection on HMMA (bf16x3)
    split_transpose_kernel<<<dim3(QKVN / 32, HID / 32), 256>>>(Wqkv, wT_hi, wT_lo, HID, QKVN);
    split_rows_kernel<<<(SLEN * HID + 255) / 256, 256>>>(hidden, a_hi, a_lo, SLEN * HID);
    gemm_mma_bf16x3<<<dim3(QKVN / 128, SLEN / 128), 256, MM_SMEM_TOT>>>(
        a_hi, a_lo, wT_hi, wT_lo, qkv, HID, QKVN);

    // 2) RMSNorm + RoPE -> bf16 hi/lo Q, K ; V transpose+split
    rmsnorm_rope_split<<<dim3(SLEN, NQH + NKVH), 128>>>(cosT, sinT, qg, kg,
                                                        q_hi, q_lo, k_hi, k_lo);
    v_split_transpose<<<dim3(SLEN / 32, HDIM / 32, NKVH), 256>>>(vt_hi, vt_lo);

    // 3) Fused flash attention -> a_hi/a_lo (O-proj input)
    flash_attn<<<dim3(NQB, NQH), 256, FA_SMEM>>>(
        q_hi, q_lo, k_hi, k_lo, vt_hi, vt_lo, a_hi, a_lo);

    // 4) Output projection on HMMA (bf16x3)
    split_transpose_kernel<<<dim3(HID / 32, HID / 32), 256>>>(Wo, wT_hi, wT_lo, HID, HID);
    gemm_mma_bf16x3<<<dim3(HID / 128, SLEN / 128), 256, MM_SMEM_TOT>>>(
        a_hi, a_lo, wT_hi, wT_lo, out, HID, HID);
}

// round 14
// speedup vs baseline: 2.6458x; 1.0207x over previous
#include <cuda_runtime.h>
#include <cuda_bf16.h>
#include <math.h>
#include <float.h>
#include <stdint.h>

#define SLEN 2048
#define HID  4096
#define NQH  32
#define NKVH 8
#define HDIM 128
#define QKVN 6144   // (32 + 2*8) * 128
#define EPSV 1e-6f
#define QBLK 128
#define NQB  (SLEN / QBLK)     // 16
#define SCALE 0.08838834764831845f
#define L2E   1.44269504088896f

// ---------------- scratch (__device__ globals; no allocation) ---------------
__device__ float g_qkv[(size_t)SLEN * QKVN];                 // 50 MB
__device__ __nv_bfloat16 g_wT_hi[(size_t)QKVN * HID];        // 50 MB
__device__ __nv_bfloat16 g_wT_lo[(size_t)QKVN * HID];        // 50 MB
__device__ __nv_bfloat16 g_a_hi[(size_t)SLEN * HID];         // 16 MB
__device__ __nv_bfloat16 g_a_lo[(size_t)SLEN * HID];         // 16 MB
__device__ __nv_bfloat16 g_q_hi[(size_t)SLEN * NQH * HDIM];  // 16 MB
__device__ __nv_bfloat16 g_q_lo[(size_t)SLEN * NQH * HDIM];  // 16 MB
__device__ __nv_bfloat16 g_k_hi[(size_t)SLEN * NKVH * HDIM]; // 4 MB
__device__ __nv_bfloat16 g_k_lo[(size_t)SLEN * NKVH * HDIM]; // 4 MB
__device__ __nv_bfloat16 g_vt_hi[(size_t)NKVH * HDIM * SLEN];// 4 MB
__device__ __nv_bfloat16 g_vt_lo[(size_t)NKVH * HDIM * SLEN];// 4 MB

// ---------------- helpers ----------------------------------------------------
__device__ __forceinline__ uint32_t smem_to_u32(const void* p) {
    uint32_t a;
    asm("{ .reg .u64 t; cvta.to.shared.u64 t, %1; cvt.u32.u64 %0, t; }" : "=r"(a) : "l"(p));
    return a;
}
__device__ __forceinline__ void cp16(uint32_t dst, const void* src) {
    asm volatile("cp.async.cg.shared.global [%0], [%1], 16;" :: "r"(dst), "l"(src));
}
__device__ __forceinline__ void ldsm4(uint32_t& r0, uint32_t& r1, uint32_t& r2, uint32_t& r3,
                                      uint32_t addr) {
    asm volatile("ldmatrix.sync.aligned.m8n8.x4.shared.b16 {%0,%1,%2,%3}, [%4];"
        : "=r"(r0), "=r"(r1), "=r"(r2), "=r"(r3) : "r"(addr));
}
__device__ __forceinline__ void mma16816(float* c, const uint32_t* a, const uint32_t* b) {
    asm volatile(
        "mma.sync.aligned.m16n8k16.row.col.f32.bf16.bf16.f32 "
        "{%0,%1,%2,%3}, {%4,%5,%6,%7}, {%8,%9}, {%0,%1,%2,%3};"
        : "+f"(c[0]), "+f"(c[1]), "+f"(c[2]), "+f"(c[3])
        : "r"(a[0]), "r"(a[1]), "r"(a[2]), "r"(a[3]), "r"(b[0]), "r"(b[1]));
}
__device__ __forceinline__ uint32_t packbf2(float a, float b) {
    __nv_bfloat162 h = __float22bfloat162_rn(make_float2(a, b));
    return *reinterpret_cast<uint32_t*>(&h);
}

// ---------------------------------------------------------------------------
// mma.sync bf16x3 GEMM, ldmatrix loads, 2 CTAs/SM.
// C[M,N] = A[M,K] * Bt[N,K]^T. CTA 128x128, 8 warps (4x2), warp 32x64.
// K chunk 32, rows padded to 80 B (stride 20 words: rows 0,20,8,28,16,4,24,12
// mod 32 -> distinct bank quads, ldmatrix conflict-free). Stage 40 KB,
// double-buffered 80 KB -> two co-resident CTAs hide barrier/fill stalls.
// ---------------------------------------------------------------------------
#define MM_KC 32
#define MM_ROWB 80
#define MM_TILE_BYTES (128 * MM_ROWB)          // 10240
#define MM_STAGE (4 * MM_TILE_BYTES)           // 40960
#define MM_SMEM_TOT (2 * MM_STAGE)             // 81920

__global__ __launch_bounds__(256, 2) void gemm_mma_bf16x3(
    const __nv_bfloat16* __restrict__ Ahi, const __nv_bfloat16* __restrict__ Alo,
    const __nv_bfloat16* __restrict__ Bthi, const __nv_bfloat16* __restrict__ Btlo,
    float* __restrict__ C, int K, int N)
{
    extern __shared__ char smem[];
    const uint32_t sbase = smem_to_u32(smem);
    const int tid = threadIdx.x;
    const int wid = tid >> 5, lane = tid & 31;
    const int wm = wid >> 1, wn = wid & 1;
    const int row0 = blockIdx.y * 128;
    const int n0 = blockIdx.x * 128;
    const int gq = lane >> 2;
    const int tq = lane & 3;
    const int l7 = lane & 7, lb8 = (lane >> 3) & 1, lb16 = (lane >> 4) & 1;

    float acc[2][8][4];
    #pragma unroll
    for (int mt = 0; mt < 2; mt++)
        #pragma unroll
        for (int nt = 0; nt < 8; nt++)
            #pragma unroll
            for (int i = 0; i < 4; i++)
                acc[mt][nt][i] = 0.f;

    const int NCH = K / MM_KC;

    auto fill = [&](int s, int c) {
        const uint32_t sb = sbase + s * MM_STAGE;
        const int k0 = c * MM_KC;
        #pragma unroll
        for (int i = 0; i < 2; i++) {
            int idx = i * 256 + tid;
            int r = idx >> 2;            // 0..127
            int seg = idx & 3;           // 4 x 16B segments per 64B row
            uint32_t dst = sb + r * MM_ROWB + seg * 16;
            size_t ao = (size_t)(row0 + r) * K + k0 + seg * 8;
            size_t bo = (size_t)(n0 + r) * K + k0 + seg * 8;
            cp16(dst,                      Ahi + ao);
            cp16(dst + MM_TILE_BYTES,      Alo + ao);
            cp16(dst + 2 * MM_TILE_BYTES,  Bthi + bo);
            cp16(dst + 3 * MM_TILE_BYTES,  Btlo + bo);
        }
        asm volatile("cp.async.commit_group;");
    };

    fill(0, 0);

    for (int c = 0; c < NCH; c++) {
        if (c + 1 < NCH) {
            fill((c + 1) & 1, c + 1);
            asm volatile("cp.async.wait_group 1;");
        } else {
            asm volatile("cp.async.wait_group 0;");
        }
        __syncthreads();

        const uint32_t sb = sbase + (c & 1) * MM_STAGE;
        #pragma unroll
        for (int ks = 0; ks < MM_KC / 16; ks++) {
            uint32_t ah[2][4], al[2][4];
            #pragma unroll
            for (int mt = 0; mt < 2; mt++) {
                uint32_t aaddr = sb + (uint32_t)((wm * 32 + mt * 16 + l7 + lb8 * 8) * MM_ROWB
                               + ks * 32 + lb16 * 16);
                ldsm4(ah[mt][0], ah[mt][1], ah[mt][2], ah[mt][3], aaddr);
                ldsm4(al[mt][0], al[mt][1], al[mt][2], al[mt][3], aaddr + MM_TILE_BYTES);
            }
            #pragma unroll
            for (int t = 0; t < 4; t++) {
                uint32_t baddr = sbase + (c & 1) * MM_STAGE + 2 * MM_TILE_BYTES
                               + (uint32_t)((wn * 64 + t * 16 + lb16 * 8 + l7) * MM_ROWB
                               + ks * 32 + lb8 * 16);
                uint32_t bh[4], bl[4];
                ldsm4(bh[0], bh[1], bh[2], bh[3], baddr);
                ldsm4(bl[0], bl[1], bl[2], bl[3], baddr + MM_TILE_BYTES);
                #pragma unroll
                for (int mt = 0; mt < 2; mt++) {
                    mma16816(acc[mt][2 * t],     ah[mt], bh + 0);
                    mma16816(acc[mt][2 * t],     ah[mt], bl + 0);
                    mma16816(acc[mt][2 * t],     al[mt], bh + 0);
                    mma16816(acc[mt][2 * t + 1], ah[mt], bh + 2);
                    mma16816(acc[mt][2 * t + 1], ah[mt], bl + 2);
                    mma16816(acc[mt][2 * t + 1], al[mt], bh + 2);
                }
            }
        }
        __syncthreads();
    }

    #pragma unroll
    for (int mt = 0; mt < 2; mt++) {
        int r = row0 + wm * 32 + mt * 16 + gq;
        #pragma unroll
        for (int nt = 0; nt < 8; nt++) {
            int cc = n0 + wn * 64 + nt * 8 + tq * 2;
            *reinterpret_cast<float2*>(&C[(size_t)r * N + cc]) =
                make_float2(acc[mt][nt][0], acc[mt][nt][1]);
            *reinterpret_cast<float2*>(&C[(size_t)(r + 8) * N + cc]) =
                make_float2(acc[mt][nt][2], acc[mt][nt][3]);
        }
    }
}

// ---------------------------------------------------------------------------
// Fused flash attention on HMMA, ldmatrix fragment loads (unchanged from R13).
// Grid (NQB, NQH), 256 threads (8 warps x 16 query rows).
// ---------------------------------------------------------------------------
#define FA_ROWB 272
#define FA_TILE (128 * FA_ROWB)     // 34816
#define FA_QHI  0
#define FA_QLO  (1 * FA_TILE)
#define FA_KHI  (2 * FA_TILE)
#define FA_KLO  (3 * FA_TILE)
#define FA_VHI  (4 * FA_TILE)
#define FA_VLO  (5 * FA_TILE)
#define FA_SMEM (6 * FA_TILE)       // 208896

__global__ __launch_bounds__(256, 1) void flash_attn(
    const __nv_bfloat16* __restrict__ qhi, const __nv_bfloat16* __restrict__ qlo,
    const __nv_bfloat16* __restrict__ khi, const __nv_bfloat16* __restrict__ klo,
    const __nv_bfloat16* __restrict__ vthi, const __nv_bfloat16* __restrict__ vtlo,
    __nv_bfloat16* __restrict__ outhi, __nv_bfloat16* __restrict__ outlo)
{
    extern __shared__ char smem[];
    const uint32_t sb = smem_to_u32(smem);
    const int tid = threadIdx.x;
    const int wid = tid >> 5, lane = tid & 31;
    const int gq = lane >> 2, tq = lane & 3;
    const int l7 = lane & 7, lb8 = (lane >> 3) & 1, lb16 = (lane >> 4) & 1;
    const int qb = (NQB - 1) - blockIdx.x;       // long blocks first
    const int h = blockIdx.y;
    const int kh = h >> 2;                       // GQA: 4 q-heads per kv-head
    const int r0 = qb * QBLK;
    const int wrow = wid * 16;

    // ---- Q tile load (once), fully waited before use ----
    {
        const __nv_bfloat16* srcH = qhi + ((size_t)r0 * NQH + h) * HDIM;
        const __nv_bfloat16* srcL = qlo + ((size_t)r0 * NQH + h) * HDIM;
        #pragma unroll
        for (int i = 0; i < 8; i++) {
            int idx = i * 256 + tid;
            int r = idx >> 4, seg = idx & 15;          // 128 rows x 16 segs
            size_t so = (size_t)r * (NQH * HDIM) + seg * 8;
            uint32_t dst = sb + r * FA_ROWB + seg * 16;
            cp16(dst + FA_QHI, srcH + so);
            cp16(dst + FA_QLO, srcL + so);
        }
        asm volatile("cp.async.commit_group;");
        asm volatile("cp.async.wait_group 0;");
    }
    __syncthreads();

    float m0 = -1e30f, m1 = -1e30f, l0 = 0.f, l1 = 0.f;
    float o[16][4];
    #pragma unroll
    for (int nt = 0; nt < 16; nt++)
        #pragma unroll
        for (int i = 0; i < 4; i++) o[nt][i] = 0.f;

    for (int j = 0; j <= qb; j++) {
        const int t0 = j * QBLK;
        // ---- K group, then V group ----
        {
            const __nv_bfloat16* srcH = khi + ((size_t)t0 * NKVH + kh) * HDIM;
            const __nv_bfloat16* srcL = klo + ((size_t)t0 * NKVH + kh) * HDIM;
            #pragma unroll
            for (int i = 0; i < 8; i++) {
                int idx = i * 256 + tid;
                int r = idx >> 4, seg = idx & 15;
                size_t so = (size_t)r * (NKVH * HDIM) + seg * 8;
                uint32_t dst = sb + r * FA_ROWB + seg * 16;
                cp16(dst + FA_KHI, srcH + so);
                cp16(dst + FA_KLO, srcL + so);
            }
            asm volatile("cp.async.commit_group;");
            const __nv_bfloat16* svH = vthi + (size_t)kh * HDIM * SLEN + t0;
            const __nv_bfloat16* svL = vtlo + (size_t)kh * HDIM * SLEN + t0;
            #pragma unroll
            for (int i = 0; i < 8; i++) {
                int idx = i * 256 + tid;
                int r = idx >> 4, seg = idx & 15;
                size_t so = (size_t)r * SLEN + seg * 8;
                uint32_t dst = sb + r * FA_ROWB + seg * 16;
                cp16(dst + FA_VHI, svH + so);
                cp16(dst + FA_VLO, svL + so);
            }
            asm volatile("cp.async.commit_group;");
        }
        asm volatile("cp.async.wait_group 1;");   // K ready; V may be in flight
        __syncthreads();

        // ---- S = Q K^T (bf16x3) ----
        float s[16][4];
        #pragma unroll
        for (int nt = 0; nt < 16; nt++)
            #pragma unroll
            for (int i = 0; i < 4; i++) s[nt][i] = 0.f;

        #pragma unroll
        for (int ks = 0; ks < 8; ks++) {
            uint32_t aaddr = sb + FA_QHI
                           + (uint32_t)((wrow + l7 + lb8 * 8) * FA_ROWB + ks * 32 + lb16 * 16);
            uint32_t ah[4], al[4];
            ldsm4(ah[0], ah[1], ah[2], ah[3], aaddr);
            ldsm4(al[0], al[1], al[2], al[3], aaddr + FA_TILE);
            #pragma unroll
            for (int t = 0; t < 8; t++) {
                uint32_t kaddr = sb + FA_KHI
                               + (uint32_t)((t * 16 + lb16 * 8 + l7) * FA_ROWB + ks * 32 + lb8 * 16);
                uint32_t bh[4], bl[4];
                ldsm4(bh[0], bh[1], bh[2], bh[3], kaddr);
                ldsm4(bl[0], bl[1], bl[2], bl[3], kaddr + FA_TILE);
                mma16816(s[2 * t],     ah, bh + 0);
                mma16816(s[2 * t],     ah, bl + 0);
                mma16816(s[2 * t],     al, bh + 0);
                mma16816(s[2 * t + 1], ah, bh + 2);
                mma16816(s[2 * t + 1], ah, bl + 2);
                mma16816(s[2 * t + 1], al, bh + 2);
            }
        }

        // ---- scale + causal mask (diagonal block only) ----
        #pragma unroll
        for (int nt = 0; nt < 16; nt++)
            #pragma unroll
            for (int i = 0; i < 4; i++) s[nt][i] *= SCALE;
        if (j == qb) {
            const int lr0 = wrow + gq, lr1 = lr0 + 8;
            #pragma unroll
            for (int nt = 0; nt < 16; nt++) {
                int c0 = nt * 8 + tq * 2;
                if (c0 > lr0)     s[nt][0] = -1e30f;
                if (c0 + 1 > lr0) s[nt][1] = -1e30f;
                if (c0 > lr1)     s[nt][2] = -1e30f;
                if (c0 + 1 > lr1) s[nt][3] = -1e30f;
            }
        }

        // ---- online softmax (quad-level row reductions) ----
        float rm0 = -1e30f, rm1 = -1e30f;
        #pragma unroll
        for (int nt = 0; nt < 16; nt++) {
            rm0 = fmaxf(rm0, fmaxf(s[nt][0], s[nt][1]));
            rm1 = fmaxf(rm1, fmaxf(s[nt][2], s[nt][3]));
        }
        rm0 = fmaxf(rm0, __shfl_xor_sync(0xffffffffu, rm0, 1));
        rm0 = fmaxf(rm0, __shfl_xor_sync(0xffffffffu, rm0, 2));
        rm1 = fmaxf(rm1, __shfl_xor_sync(0xffffffffu, rm1, 1));
        rm1 = fmaxf(rm1, __shfl_xor_sync(0xffffffffu, rm1, 2));
        float mn0 = fmaxf(m0, rm0), mn1 = fmaxf(m1, rm1);
        float al0 = exp2f((m0 - mn0) * L2E), al1 = exp2f((m1 - mn1) * L2E);

        // ---- P = exp(S - m), split hi/lo for 3-MMA PV ----
        float sum0 = 0.f, sum1 = 0.f;
        uint32_t pbh[16][2], pbl[16][2];
        #pragma unroll
        for (int nt = 0; nt < 16; nt++) {
            float p0 = exp2f((s[nt][0] - mn0) * L2E);
            float p1 = exp2f((s[nt][1] - mn0) * L2E);
            float p2 = exp2f((s[nt][2] - mn1) * L2E);
            float p3 = exp2f((s[nt][3] - mn1) * L2E);
            sum0 += p0 + p1;
            sum1 += p2 + p3;
            __nv_bfloat16 h0 = __float2bfloat16(p0), h1 = __float2bfloat16(p1);
            __nv_bfloat16 h2 = __float2bfloat16(p2), h3 = __float2bfloat16(p3);
            pbh[nt][0] = packbf2(__bfloat162float(h0), __bfloat162float(h1));
            pbh[nt][1] = packbf2(__bfloat162float(h2), __bfloat162float(h3));
            pbl[nt][0] = packbf2(p0 - __bfloat162float(h0), p1 - __bfloat162float(h1));
            pbl[nt][1] = packbf2(p2 - __bfloat162float(h2), p3 - __bfloat162float(h3));
        }
        sum0 += __shfl_xor_sync(0xffffffffu, sum0, 1);
        sum0 += __shfl_xor_sync(0xffffffffu, sum0, 2);
        sum1 += __shfl_xor_sync(0xffffffffu, sum1, 1);
        sum1 += __shfl_xor_sync(0xffffffffu, sum1, 2);
        l0 = l0 * al0 + sum0;
        l1 = l1 * al1 + sum1;
        m0 = mn0; m1 = mn1;
        #pragma unroll
        for (int nt = 0; nt < 16; nt++) {
            o[nt][0] *= al0; o[nt][1] *= al0;
            o[nt][2] *= al1; o[nt][3] *= al1;
        }

        // ---- O += Phi*Vhi + Phi*Vlo + Plo*Vhi ----
        asm volatile("cp.async.wait_group 0;");
        __syncthreads();
        #pragma unroll
        for (int kt = 0; kt < 8; kt++) {
            uint32_t ah2[4] = { pbh[2 * kt][0], pbh[2 * kt][1],
                                pbh[2 * kt + 1][0], pbh[2 * kt + 1][1] };
            uint32_t al2[4] = { pbl[2 * kt][0], pbl[2 * kt][1],
                                pbl[2 * kt + 1][0], pbl[2 * kt + 1][1] };
            #pragma unroll
            for (int t = 0; t < 8; t++) {
                uint32_t vaddr = sb + FA_VHI
                               + (uint32_t)((t * 16 + lb16 * 8 + l7) * FA_ROWB + kt * 32 + lb8 * 16);
                uint32_t bh[4], bl[4];
                ldsm4(bh[0], bh[1], bh[2], bh[3], vaddr);
                ldsm4(bl[0], bl[1], bl[2], bl[3], vaddr + FA_TILE);
                mma16816(o[2 * t],     ah2, bh + 0);
                mma16816(o[2 * t],     ah2, bl + 0);
                mma16816(o[2 * t],     al2, bh + 0);
                mma16816(o[2 * t + 1], ah2, bh + 2);
                mma16816(o[2 * t + 1], ah2, bl + 2);
                mma16816(o[2 * t + 1], al2, bh + 2);
            }
        }
        __syncthreads();   // all K/V reads done before next iter overwrites
    }

    // ---- epilogue: normalize + split to bf16 hi/lo ----
    const float inv0 = 1.f / fmaxf(l0, 1e-20f);
    const float inv1 = 1.f / fmaxf(l1, 1e-20f);
    const int grow0 = r0 + wrow + gq, grow1 = grow0 + 8;
    #pragma unroll
    for (int nt = 0; nt < 16; nt++) {
        int c = h * HDIM + nt * 8 + tq * 2;
        float f0 = o[nt][0] * inv0, f1 = o[nt][1] * inv0;
        float f2 = o[nt][2] * inv1, f3 = o[nt][3] * inv1;
        __nv_bfloat16 h0 = __float2bfloat16(f0), h1 = __float2bfloat16(f1);
        __nv_bfloat16 h2 = __float2bfloat16(f2), h3 = __float2bfloat16(f3);
        __nv_bfloat16 e0 = __float2bfloat16(f0 - __bfloat162float(h0));
        __nv_bfloat16 e1 = __float2bfloat16(f1 - __bfloat162float(h1));
        __nv_bfloat16 e2 = __float2bfloat16(f2 - __bfloat162float(h2));
        __nv_bfloat16 e3 = __float2bfloat16(f3 - __bfloat162float(h3));
        *reinterpret_cast<__nv_bfloat162*>(&outhi[(size_t)grow0 * HID + c]) =
            __nv_bfloat162(h0, h1);
        *reinterpret_cast<__nv_bfloat162*>(&outlo[(size_t)grow0 * HID + c]) =
            __nv_bfloat162(e0, e1);
        *reinterpret_cast<__nv_bfloat162*>(&outhi[(size_t)grow1 * HID + c]) =
            __nv_bfloat162(h2, h3);
        *reinterpret_cast<__nv_bfloat162*>(&outlo[(size_t)grow1 * HID + c]) =
            __nv_bfloat162(e2, e3);
    }
}

// ---------------------------------------------------------------------------
// RMSNorm + RoPE, reading fp32 qkv, writing bf16 hi/lo Q and K buffers.
// ---------------------------------------------------------------------------
__global__ __launch_bounds__(128) void rmsnorm_rope_split(
    const float* __restrict__ cosT, const float* __restrict__ sinT,
    const float* __restrict__ q_gamma, const float* __restrict__ k_gamma,
    __nv_bfloat16* __restrict__ qhi, __nv_bfloat16* __restrict__ qlo,
    __nv_bfloat16* __restrict__ khi, __nv_bfloat16* __restrict__ klo)
{
    const int s = blockIdx.x;
    const int h = blockIdx.y;           // 0..39
    const float* x;
    const float* gamma;
    __nv_bfloat16 *dh, *dl;
    if (h < NQH) {
        x = g_qkv + (size_t)s * QKVN + h * HDIM;
        gamma = q_gamma;
        dh = qhi + ((size_t)s * NQH + h) * HDIM;
        dl = qlo + ((size_t)s * NQH + h) * HDIM;
    } else {
        x = g_qkv + (size_t)s * QKVN + NQH * HDIM + (h - NQH) * HDIM;
        gamma = k_gamma;
        dh = khi + ((size_t)s * NKVH + (h - NQH)) * HDIM;
        dl = klo + ((size_t)s * NKVH + (h - NQH)) * HDIM;
    }

    const int tid = threadIdx.x;
    float v = x[tid];
    float sq = v * v;
    #pragma unroll
    for (int o = 16; o > 0; o >>= 1) sq += __shfl_xor_sync(0xffffffffu, sq, o);
    __shared__ float ws[4];
    if ((tid & 31) == 0) ws[tid >> 5] = sq;
    __syncthreads();
    float total = ws[0] + ws[1] + ws[2] + ws[3];
    float rinv = rsqrtf(total * (1.0f / HDIM) + EPSV);

    __shared__ float xn[HDIM];
    xn[tid] = v * rinv * gamma[tid];
    __syncthreads();

    if (tid < 64) {
        float c = cosT[(size_t)s * 64 + tid];
        float sn = sinT[(size_t)s * 64 + tid];
        float x1 = xn[tid];
        float x2 = xn[tid + 64];
        float y1 = x1 * c - x2 * sn;
        float y2 = x2 * c + x1 * sn;
        __nv_bfloat16 h1 = __float2bfloat16(y1);
        __nv_bfloat16 h2 = __float2bfloat16(y2);
        dh[tid] = h1;
        dh[tid + 64] = h2;
        dl[tid] = __float2bfloat16(y1 - __bfloat162float(h1));
        dl[tid + 64] = __float2bfloat16(y2 - __bfloat162float(h2));
    }
}

// ---------------------------------------------------------------------------
// V: fp32 [seq][kvh*128 cols] -> transposed bf16 hi/lo [kvh][d][seq]
// ---------------------------------------------------------------------------
__global__ __launch_bounds__(256) void v_split_transpose(
    __nv_bfloat16* __restrict__ TH, __nv_bfloat16* __restrict__ TL)
{
    __shared__ float t[32][33];
    const int t0 = blockIdx.x * 32;
    const int d0 = blockIdx.y * 32;
    const int kh = blockIdx.z;
    const int tx = threadIdx.x & 31, ty = threadIdx.x >> 5;
    #pragma unroll
    for (int i = 0; i < 4; i++)
        t[ty + 8 * i][tx] =
            g_qkv[(size_t)(t0 + ty + 8 * i) * QKVN + (NQH + NKVH) * HDIM + kh * HDIM + d0 + tx];
    __syncthreads();
    #pragma unroll
    for (int i = 0; i < 4; i++) {
        float x = t[tx][ty + 8 * i];
        __nv_bfloat16 h = __float2bfloat16(x);
        size_t o = ((size_t)kh * HDIM + d0 + ty + 8 * i) * SLEN + t0 + tx;
        TH[o] = h;
        TL[o] = __float2bfloat16(x - __bfloat162float(h));
    }
}

// ---------------------------------------------------------------------------
// fp32 -> bf16 hi/lo split (elementwise)
// ---------------------------------------------------------------------------
__global__ void split_rows_kernel(const float* __restrict__ X,
                                  __nv_bfloat16* __restrict__ H,
                                  __nv_bfloat16* __restrict__ L, int n)
{
    int i = blockIdx.x * blockDim.x + threadIdx.x;
    if (i < n) {
        float x = X[i];
        __nv_bfloat16 h = __float2bfloat16(x);
        H[i] = h;
        L[i] = __float2bfloat16(x - __bfloat162float(h));
    }
}

// fp32 [K,N] -> transposed bf16 hi/lo [N,K]
__global__ __launch_bounds__(256) void split_transpose_kernel(
    const float* __restrict__ W, __nv_bfloat16* __restrict__ TH,
    __nv_bfloat16* __restrict__ TL, int K, int N)
{
    __shared__ float t[32][33];
    const int n0 = blockIdx.x * 32, k0 = blockIdx.y * 32;
    const int tx = threadIdx.x & 31, ty = threadIdx.x >> 5;
    #pragma unroll
    for (int i = 0; i < 4; i++)
        t[ty + 8 * i][tx] = W[(size_t)(k0 + ty + 8 * i) * N + n0 + tx];
    __syncthreads();
    #pragma unroll
    for (int i = 0; i < 4; i++) {
        float x = t[tx][ty + 8 * i];
        __nv_bfloat16 h = __float2bfloat16(x);
        size_t o = (size_t)(n0 + ty + 8 * i) * K + k0 + tx;
        TH[o] = h;
        TL[o] = __float2bfloat16(x - __bfloat162float(h));
    }
}

// ---------------------------------------------------------------------------
// launch
// ---------------------------------------------------------------------------
extern "C" void kernel_launch(void* const* d_in, const int* in_sizes, int n_in,
                              void* d_out, int out_size)
{
    (void)in_sizes; (void)n_in; (void)out_size;
    const float* hidden = (const float*)d_in[1];
    const float* Wqkv   = (const float*)d_in[2];
    const float* Wo     = (const float*)d_in[3];
    const float* qg     = (const float*)d_in[4];
    const float* kg     = (const float*)d_in[5];
    const float* cosT   = (const float*)d_in[6];
    const float* sinT   = (const float*)d_in[7];
    float* out = (float*)d_out;

    float* qkv;
    __nv_bfloat16 *wT_hi, *wT_lo, *a_hi, *a_lo;
    __nv_bfloat16 *q_hi, *q_lo, *k_hi, *k_lo, *vt_hi, *vt_lo;
    cudaGetSymbolAddress((void**)&qkv, g_qkv);
    cudaGetSymbolAddress((void**)&wT_hi, g_wT_hi);
    cudaGetSymbolAddress((void**)&wT_lo, g_wT_lo);
    cudaGetSymbolAddress((void**)&a_hi, g_a_hi);
    cudaGetSymbolAddress((void**)&a_lo, g_a_lo);
    cudaGetSymbolAddress((void**)&q_hi, g_q_hi);
    cudaGetSymbolAddress((void**)&q_lo, g_q_lo);
    cudaGetSymbolAddress((void**)&k_hi, g_k_hi);
    cudaGetSymbolAddress((void**)&k_lo, g_k_lo);
    cudaGetSymbolAddress((void**)&vt_hi, g_vt_hi);
    cudaGetSymbolAddress((void**)&vt_lo, g_vt_lo);

    cudaFuncSetAttribute(gemm_mma_bf16x3, cudaFuncAttributeMaxDynamicSharedMemorySize, MM_SMEM_TOT);
    cudaFuncSetAttribute(flash_attn, cudaFuncAttributeMaxDynamicSharedMemorySize, FA_SMEM);

    // 1) QKV projection on HMMA (bf16x3)
    split_transpose_kernel<<<dim3(QKVN / 32, HID / 32), 256>>>(Wqkv, wT_hi, wT_lo, HID, QKVN);
    split_rows_kernel<<<(SLEN * HID + 255) / 256, 256>>>(hidden, a_hi, a_lo, SLEN * HID);
    gemm_mma_bf16x3<<<dim3(QKVN / 128, SLEN / 128), 256, MM_SMEM_TOT>>>(
        a_hi, a_lo, wT_hi, wT_lo, qkv, HID, QKVN);

    // 2) RMSNorm + RoPE -> bf16 hi/lo Q, K ; V transpose+split
    rmsnorm_rope_split<<<dim3(SLEN, NQH + NKVH), 128>>>(cosT, sinT, qg, kg,
                                                        q_hi, q_lo, k_hi, k_lo);
    v_split_transpose<<<dim3(SLEN / 32, HDIM / 32, NKVH), 256>>>(vt_hi, vt_lo);

    // 3) Fused flash attention -> a_hi/a_lo (O-proj input)
    flash_attn<<<dim3(NQB, NQH), 256, FA_SMEM>>>(
        q_hi, q_lo, k_hi, k_lo, vt_hi, vt_lo, a_hi, a_lo);

    // 4) Output projection on HMMA (bf16x3)
    split_transpose_kernel<<<dim3(HID / 32, HID / 32), 256>>>(Wo, wT_hi, wT_lo, HID, HID);
    gemm_mma_bf16x3<<<dim3(HID / 128, SLEN / 128), 256, MM_SMEM_TOT>>>(
        a_hi, a_lo, wT_hi, wT_lo, out, HID, HID);
}

// round 15
// speedup vs baseline: 3.4819x; 1.3160x over previous
#include <cuda_runtime.h>
#include <cuda_bf16.h>
#include <cuda_fp16.h>
#include <math.h>
#include <float.h>
#include <stdint.h>

#define SLEN 2048
#define HID  4096
#define NQH  32
#define NKVH 8
#define HDIM 128
#define QKVN 6144   // (32 + 2*8) * 128
#define EPSV 1e-6f
#define QBLK 128
#define NQB  (SLEN / QBLK)     // 16
#define SCALE 0.08838834764831845f
#define L2E   1.44269504088896f

// ---------------- scratch (__device__ globals; no allocation) ---------------
__device__ float g_qkv[(size_t)SLEN * QKVN];                 // 50 MB
__device__ __half g_wT_hi[(size_t)QKVN * HID];               // 50 MB (weights hi only)
__device__ __half g_a_hi[(size_t)SLEN * HID];                // 16 MB
__device__ __half g_a_lo[(size_t)SLEN * HID];                // 16 MB
__device__ __nv_bfloat16 g_q_hi[(size_t)SLEN * NQH * HDIM];  // 16 MB
__device__ __nv_bfloat16 g_q_lo[(size_t)SLEN * NQH * HDIM];  // 16 MB
__device__ __nv_bfloat16 g_k_hi[(size_t)SLEN * NKVH * HDIM]; // 4 MB
__device__ __nv_bfloat16 g_k_lo[(size_t)SLEN * NKVH * HDIM]; // 4 MB
__device__ __half g_vt_hi[(size_t)NKVH * HDIM * SLEN];       // 4 MB
__device__ __half g_vt_lo[(size_t)NKVH * HDIM * SLEN];       // 4 MB

// ---------------- helpers ----------------------------------------------------
__device__ __forceinline__ uint32_t smem_to_u32(const void* p) {
    uint32_t a;
    asm("{ .reg .u64 t; cvta.to.shared.u64 t, %1; cvt.u32.u64 %0, t; }" : "=r"(a) : "l"(p));
    return a;
}
__device__ __forceinline__ void cp16(uint32_t dst, const void* src) {
    asm volatile("cp.async.cg.shared.global [%0], [%1], 16;" :: "r"(dst), "l"(src));
}
__device__ __forceinline__ void ldsm4(uint32_t& r0, uint32_t& r1, uint32_t& r2, uint32_t& r3,
                                      uint32_t addr) {
    asm volatile("ldmatrix.sync.aligned.m8n8.x4.shared.b16 {%0,%1,%2,%3}, [%4];"
        : "=r"(r0), "=r"(r1), "=r"(r2), "=r"(r3) : "r"(addr));
}
// bf16 mma (flash QK^T)
__device__ __forceinline__ void mma16816(float* c, const uint32_t* a, const uint32_t* b) {
    asm volatile(
        "mma.sync.aligned.m16n8k16.row.col.f32.bf16.bf16.f32 "
        "{%0,%1,%2,%3}, {%4,%5,%6,%7}, {%8,%9}, {%0,%1,%2,%3};"
        : "+f"(c[0]), "+f"(c[1]), "+f"(c[2]), "+f"(c[3])
        : "r"(a[0]), "r"(a[1]), "r"(a[2]), "r"(a[3]), "r"(b[0]), "r"(b[1]));
}
// fp16 mma (dense GEMMs + flash PV)
__device__ __forceinline__ void mma16816h(float* c, const uint32_t* a, const uint32_t* b) {
    asm volatile(
        "mma.sync.aligned.m16n8k16.row.col.f32.f16.f16.f32 "
        "{%0,%1,%2,%3}, {%4,%5,%6,%7}, {%8,%9}, {%0,%1,%2,%3};"
        : "+f"(c[0]), "+f"(c[1]), "+f"(c[2]), "+f"(c[3])
        : "r"(a[0]), "r"(a[1]), "r"(a[2]), "r"(a[3]), "r"(b[0]), "r"(b[1]));
}
__device__ __forceinline__ uint32_t packbf2(float a, float b) {
    __nv_bfloat162 h = __float22bfloat162_rn(make_float2(a, b));
    return *reinterpret_cast<uint32_t*>(&h);
}
__device__ __forceinline__ uint32_t packh2(float a, float b) {
    __half2 h = __floats2half2_rn(a, b);
    return *reinterpret_cast<uint32_t*>(&h);
}

// ---------------------------------------------------------------------------
// fp16x2 GEMM: C[M,N] = (Ah+Al)[M,K] * Bh[N,K]^T, fp32 accumulate.
// A = activations split fp16 hi/lo (22-bit); B = weights fp16 hi only.
// CTA 128x128, 8 warps (4x2), K chunk 32, 80B padded rows, 2 CTAs/SM.
// ---------------------------------------------------------------------------
#define MM_KC 32
#define MM_ROWB 80
#define MM_TILE_BYTES (128 * MM_ROWB)          // 10240
#define MM_STAGE (3 * MM_TILE_BYTES)           // 30720 (Ah, Al, Bh)
#define MM_SMEM_TOT (2 * MM_STAGE)             // 61440

__global__ __launch_bounds__(256, 2) void gemm_fp16x2(
    const __half* __restrict__ Ahi, const __half* __restrict__ Alo,
    const __half* __restrict__ Bth,
    float* __restrict__ C, int K, int N)
{
    extern __shared__ char smem[];
    const uint32_t sbase = smem_to_u32(smem);
    const int tid = threadIdx.x;
    const int wid = tid >> 5, lane = tid & 31;
    const int wm = wid >> 1, wn = wid & 1;
    const int row0 = blockIdx.y * 128;
    const int n0 = blockIdx.x * 128;
    const int gq = lane >> 2;
    const int tq = lane & 3;
    const int l7 = lane & 7, lb8 = (lane >> 3) & 1, lb16 = (lane >> 4) & 1;

    float acc[2][8][4];
    #pragma unroll
    for (int mt = 0; mt < 2; mt++)
        #pragma unroll
        for (int nt = 0; nt < 8; nt++)
            #pragma unroll
            for (int i = 0; i < 4; i++)
                acc[mt][nt][i] = 0.f;

    const int NCH = K / MM_KC;

    auto fill = [&](int s, int c) {
        const uint32_t sb = sbase + s * MM_STAGE;
        const int k0 = c * MM_KC;
        #pragma unroll
        for (int i = 0; i < 2; i++) {
            int idx = i * 256 + tid;
            int r = idx >> 2;            // 0..127
            int seg = idx & 3;           // 4 x 16B segments per 64B row
            uint32_t dst = sb + r * MM_ROWB + seg * 16;
            size_t ao = (size_t)(row0 + r) * K + k0 + seg * 8;
            size_t bo = (size_t)(n0 + r) * K + k0 + seg * 8;
            cp16(dst,                      Ahi + ao);
            cp16(dst + MM_TILE_BYTES,      Alo + ao);
            cp16(dst + 2 * MM_TILE_BYTES,  Bth + bo);
        }
        asm volatile("cp.async.commit_group;");
    };

    fill(0, 0);

    for (int c = 0; c < NCH; c++) {
        if (c + 1 < NCH) {
            fill((c + 1) & 1, c + 1);
            asm volatile("cp.async.wait_group 1;");
        } else {
            asm volatile("cp.async.wait_group 0;");
        }
        __syncthreads();

        const uint32_t sb = sbase + (c & 1) * MM_STAGE;
        #pragma unroll
        for (int ks = 0; ks < MM_KC / 16; ks++) {
            uint32_t ah[2][4], al[2][4];
            #pragma unroll
            for (int mt = 0; mt < 2; mt++) {
                uint32_t aaddr = sb + (uint32_t)((wm * 32 + mt * 16 + l7 + lb8 * 8) * MM_ROWB
                               + ks * 32 + lb16 * 16);
                ldsm4(ah[mt][0], ah[mt][1], ah[mt][2], ah[mt][3], aaddr);
                ldsm4(al[mt][0], al[mt][1], al[mt][2], al[mt][3], aaddr + MM_TILE_BYTES);
            }
            #pragma unroll
            for (int t = 0; t < 4; t++) {
                uint32_t baddr = sb + 2 * MM_TILE_BYTES
                               + (uint32_t)((wn * 64 + t * 16 + lb16 * 8 + l7) * MM_ROWB
                               + ks * 32 + lb8 * 16);
                uint32_t bh[4];
                ldsm4(bh[0], bh[1], bh[2], bh[3], baddr);
                #pragma unroll
                for (int mt = 0; mt < 2; mt++) {
                    mma16816h(acc[mt][2 * t],     ah[mt], bh + 0);
                    mma16816h(acc[mt][2 * t],     al[mt], bh + 0);
                    mma16816h(acc[mt][2 * t + 1], ah[mt], bh + 2);
                    mma16816h(acc[mt][2 * t + 1], al[mt], bh + 2);
                }
            }
        }
        __syncthreads();
    }

    #pragma unroll
    for (int mt = 0; mt < 2; mt++) {
        int r = row0 + wm * 32 + mt * 16 + gq;
        #pragma unroll
        for (int nt = 0; nt < 8; nt++) {
            int cc = n0 + wn * 64 + nt * 8 + tq * 2;
            *reinterpret_cast<float2*>(&C[(size_t)r * N + cc]) =
                make_float2(acc[mt][nt][0], acc[mt][nt][1]);
            *reinterpret_cast<float2*>(&C[(size_t)(r + 8) * N + cc]) =
                make_float2(acc[mt][nt][2], acc[mt][nt][3]);
        }
    }
}

// ---------------------------------------------------------------------------
// Fused flash attention: QK^T bf16x3 (exp-sensitive), PV fp16x2 (P hi, V hi+lo).
// Grid (NQB, NQH), 256 threads (8 warps x 16 query rows).
// ---------------------------------------------------------------------------
#define FA_ROWB 272
#define FA_TILE (128 * FA_ROWB)     // 34816
#define FA_QHI  0
#define FA_QLO  (1 * FA_TILE)
#define FA_KHI  (2 * FA_TILE)
#define FA_KLO  (3 * FA_TILE)
#define FA_VHI  (4 * FA_TILE)
#define FA_VLO  (5 * FA_TILE)
#define FA_SMEM (6 * FA_TILE)       // 208896

__global__ __launch_bounds__(256, 1) void flash_attn(
    const __nv_bfloat16* __restrict__ qhi, const __nv_bfloat16* __restrict__ qlo,
    const __nv_bfloat16* __restrict__ khi, const __nv_bfloat16* __restrict__ klo,
    const __half* __restrict__ vthi, const __half* __restrict__ vtlo,
    __half* __restrict__ outhi, __half* __restrict__ outlo)
{
    extern __shared__ char smem[];
    const uint32_t sb = smem_to_u32(smem);
    const int tid = threadIdx.x;
    const int wid = tid >> 5, lane = tid & 31;
    const int gq = lane >> 2, tq = lane & 3;
    const int l7 = lane & 7, lb8 = (lane >> 3) & 1, lb16 = (lane >> 4) & 1;
    const int qb = (NQB - 1) - blockIdx.x;       // long blocks first
    const int h = blockIdx.y;
    const int kh = h >> 2;                       // GQA: 4 q-heads per kv-head
    const int r0 = qb * QBLK;
    const int wrow = wid * 16;

    // ---- Q tile load (once), fully waited before use ----
    {
        const __nv_bfloat16* srcH = qhi + ((size_t)r0 * NQH + h) * HDIM;
        const __nv_bfloat16* srcL = qlo + ((size_t)r0 * NQH + h) * HDIM;
        #pragma unroll
        for (int i = 0; i < 8; i++) {
            int idx = i * 256 + tid;
            int r = idx >> 4, seg = idx & 15;          // 128 rows x 16 segs
            size_t so = (size_t)r * (NQH * HDIM) + seg * 8;
            uint32_t dst = sb + r * FA_ROWB + seg * 16;
            cp16(dst + FA_QHI, srcH + so);
            cp16(dst + FA_QLO, srcL + so);
        }
        asm volatile("cp.async.commit_group;");
        asm volatile("cp.async.wait_group 0;");
    }
    __syncthreads();

    float m0 = -1e30f, m1 = -1e30f, l0 = 0.f, l1 = 0.f;
    float o[16][4];
    #pragma unroll
    for (int nt = 0; nt < 16; nt++)
        #pragma unroll
        for (int i = 0; i < 4; i++) o[nt][i] = 0.f;

    for (int j = 0; j <= qb; j++) {
        const int t0 = j * QBLK;
        // ---- K group, then V group ----
        {
            const __nv_bfloat16* srcH = khi + ((size_t)t0 * NKVH + kh) * HDIM;
            const __nv_bfloat16* srcL = klo + ((size_t)t0 * NKVH + kh) * HDIM;
            #pragma unroll
            for (int i = 0; i < 8; i++) {
                int idx = i * 256 + tid;
                int r = idx >> 4, seg = idx & 15;
                size_t so = (size_t)r * (NKVH * HDIM) + seg * 8;
                uint32_t dst = sb + r * FA_ROWB + seg * 16;
                cp16(dst + FA_KHI, srcH + so);
                cp16(dst + FA_KLO, srcL + so);
            }
            asm volatile("cp.async.commit_group;");
            const __half* svH = vthi + (size_t)kh * HDIM * SLEN + t0;
            const __half* svL = vtlo + (size_t)kh * HDIM * SLEN + t0;
            #pragma unroll
            for (int i = 0; i < 8; i++) {
                int idx = i * 256 + tid;
                int r = idx >> 4, seg = idx & 15;
                size_t so = (size_t)r * SLEN + seg * 8;
                uint32_t dst = sb + r * FA_ROWB + seg * 16;
                cp16(dst + FA_VHI, svH + so);
                cp16(dst + FA_VLO, svL + so);
            }
            asm volatile("cp.async.commit_group;");
        }
        asm volatile("cp.async.wait_group 1;");   // K ready; V may be in flight
        __syncthreads();

        // ---- S = Q K^T (bf16x3) ----
        float s[16][4];
        #pragma unroll
        for (int nt = 0; nt < 16; nt++)
            #pragma unroll
            for (int i = 0; i < 4; i++) s[nt][i] = 0.f;

        #pragma unroll
        for (int ks = 0; ks < 8; ks++) {
            uint32_t aaddr = sb + FA_QHI
                           + (uint32_t)((wrow + l7 + lb8 * 8) * FA_ROWB + ks * 32 + lb16 * 16);
            uint32_t ah[4], al[4];
            ldsm4(ah[0], ah[1], ah[2], ah[3], aaddr);
            ldsm4(al[0], al[1], al[2], al[3], aaddr + FA_TILE);
            #pragma unroll
            for (int t = 0; t < 8; t++) {
                uint32_t kaddr = sb + FA_KHI
                               + (uint32_t)((t * 16 + lb16 * 8 + l7) * FA_ROWB + ks * 32 + lb8 * 16);
                uint32_t bh[4], bl[4];
                ldsm4(bh[0], bh[1], bh[2], bh[3], kaddr);
                ldsm4(bl[0], bl[1], bl[2], bl[3], kaddr + FA_TILE);
                mma16816(s[2 * t],     ah, bh + 0);
                mma16816(s[2 * t],     ah, bl + 0);
                mma16816(s[2 * t],     al, bh + 0);
                mma16816(s[2 * t + 1], ah, bh + 2);
                mma16816(s[2 * t + 1], ah, bl + 2);
                mma16816(s[2 * t + 1], al, bh + 2);
            }
        }

        // ---- scale + causal mask (diagonal block only) ----
        #pragma unroll
        for (int nt = 0; nt < 16; nt++)
            #pragma unroll
            for (int i = 0; i < 4; i++) s[nt][i] *= SCALE;
        if (j == qb) {
            const int lr0 = wrow + gq, lr1 = lr0 + 8;
            #pragma unroll
            for (int nt = 0; nt < 16; nt++) {
                int c0 = nt * 8 + tq * 2;
                if (c0 > lr0)     s[nt][0] = -1e30f;
                if (c0 + 1 > lr0) s[nt][1] = -1e30f;
                if (c0 > lr1)     s[nt][2] = -1e30f;
                if (c0 + 1 > lr1) s[nt][3] = -1e30f;
            }
        }

        // ---- online softmax (quad-level row reductions) ----
        float rm0 = -1e30f, rm1 = -1e30f;
        #pragma unroll
        for (int nt = 0; nt < 16; nt++) {
            rm0 = fmaxf(rm0, fmaxf(s[nt][0], s[nt][1]));
            rm1 = fmaxf(rm1, fmaxf(s[nt][2], s[nt][3]));
        }
        rm0 = fmaxf(rm0, __shfl_xor_sync(0xffffffffu, rm0, 1));
        rm0 = fmaxf(rm0, __shfl_xor_sync(0xffffffffu, rm0, 2));
        rm1 = fmaxf(rm1, __shfl_xor_sync(0xffffffffu, rm1, 1));
        rm1 = fmaxf(rm1, __shfl_xor_sync(0xffffffffu, rm1, 2));
        float mn0 = fmaxf(m0, rm0), mn1 = fmaxf(m1, rm1);
        float al0 = exp2f((m0 - mn0) * L2E), al1 = exp2f((m1 - mn1) * L2E);

        // ---- P = exp(S - m), fp16 hi only ----
        float sum0 = 0.f, sum1 = 0.f;
        uint32_t pbh[16][2];
        #pragma unroll
        for (int nt = 0; nt < 16; nt++) {
            float p0 = exp2f((s[nt][0] - mn0) * L2E);
            float p1 = exp2f((s[nt][1] - mn0) * L2E);
            float p2 = exp2f((s[nt][2] - mn1) * L2E);
            float p3 = exp2f((s[nt][3] - mn1) * L2E);
            sum0 += p0 + p1;
            sum1 += p2 + p3;
            pbh[nt][0] = packh2(p0, p1);
            pbh[nt][1] = packh2(p2, p3);
        }
        sum0 += __shfl_xor_sync(0xffffffffu, sum0, 1);
        sum0 += __shfl_xor_sync(0xffffffffu, sum0, 2);
        sum1 += __shfl_xor_sync(0xffffffffu, sum1, 1);
        sum1 += __shfl_xor_sync(0xffffffffu, sum1, 2);
        l0 = l0 * al0 + sum0;
        l1 = l1 * al1 + sum1;
        m0 = mn0; m1 = mn1;
        #pragma unroll
        for (int nt = 0; nt < 16; nt++) {
            o[nt][0] *= al0; o[nt][1] *= al0;
            o[nt][2] *= al1; o[nt][3] *= al1;
        }

        // ---- O += Ph*Vhi + Ph*Vlo (fp16) ----
        asm volatile("cp.async.wait_group 0;");
        __syncthreads();
        #pragma unroll
        for (int kt = 0; kt < 8; kt++) {
            uint32_t ah2[4] = { pbh[2 * kt][0], pbh[2 * kt][1],
                                pbh[2 * kt + 1][0], pbh[2 * kt + 1][1] };
            #pragma unroll
            for (int t = 0; t < 8; t++) {
                uint32_t vaddr = sb + FA_VHI
                               + (uint32_t)((t * 16 + lb16 * 8 + l7) * FA_ROWB + kt * 32 + lb8 * 16);
                uint32_t bh[4], bl[4];
                ldsm4(bh[0], bh[1], bh[2], bh[3], vaddr);
                ldsm4(bl[0], bl[1], bl[2], bl[3], vaddr + FA_TILE);
                mma16816h(o[2 * t],     ah2, bh + 0);
                mma16816h(o[2 * t],     ah2, bl + 0);
                mma16816h(o[2 * t + 1], ah2, bh + 2);
                mma16816h(o[2 * t + 1], ah2, bl + 2);
            }
        }
        __syncthreads();   // all K/V reads done before next iter overwrites
    }

    // ---- epilogue: normalize + split to fp16 hi/lo ----
    const float inv0 = 1.f / fmaxf(l0, 1e-20f);
    const float inv1 = 1.f / fmaxf(l1, 1e-20f);
    const int grow0 = r0 + wrow + gq, grow1 = grow0 + 8;
    #pragma unroll
    for (int nt = 0; nt < 16; nt++) {
        int c = h * HDIM + nt * 8 + tq * 2;
        float f0 = o[nt][0] * inv0, f1 = o[nt][1] * inv0;
        float f2 = o[nt][2] * inv1, f3 = o[nt][3] * inv1;
        __half h0 = __float2half_rn(f0), h1 = __float2half_rn(f1);
        __half h2 = __float2half_rn(f2), h3 = __float2half_rn(f3);
        __half e0 = __float2half_rn(f0 - __half2float(h0));
        __half e1 = __float2half_rn(f1 - __half2float(h1));
        __half e2 = __float2half_rn(f2 - __half2float(h2));
        __half e3 = __float2half_rn(f3 - __half2float(h3));
        *reinterpret_cast<__half2*>(&outhi[(size_t)grow0 * HID + c]) = __half2(h0, h1);
        *reinterpret_cast<__half2*>(&outlo[(size_t)grow0 * HID + c]) = __half2(e0, e1);
        *reinterpret_cast<__half2*>(&outhi[(size_t)grow1 * HID + c]) = __half2(h2, h3);
        *reinterpret_cast<__half2*>(&outlo[(size_t)grow1 * HID + c]) = __half2(e2, e3);
    }
}

// ---------------------------------------------------------------------------
// RMSNorm + RoPE -> bf16 hi/lo Q and K (unchanged).
// ---------------------------------------------------------------------------
__global__ __launch_bounds__(128) void rmsnorm_rope_split(
    const float* __restrict__ cosT, const float* __restrict__ sinT,
    const float* __restrict__ q_gamma, const float* __restrict__ k_gamma,
    __nv_bfloat16* __restrict__ qhi, __nv_bfloat16* __restrict__ qlo,
    __nv_bfloat16* __restrict__ khi, __nv_bfloat16* __restrict__ klo)
{
    const int s = blockIdx.x;
    const int h = blockIdx.y;           // 0..39
    const float* x;
    const float* gamma;
    __nv_bfloat16 *dh, *dl;
    if (h < NQH) {
        x = g_qkv + (size_t)s * QKVN + h * HDIM;
        gamma = q_gamma;
        dh = qhi + ((size_t)s * NQH + h) * HDIM;
        dl = qlo + ((size_t)s * NQH + h) * HDIM;
    } else {
        x = g_qkv + (size_t)s * QKVN + NQH * HDIM + (h - NQH) * HDIM;
        gamma = k_gamma;
        dh = khi + ((size_t)s * NKVH + (h - NQH)) * HDIM;
        dl = klo + ((size_t)s * NKVH + (h - NQH)) * HDIM;
    }

    const int tid = threadIdx.x;
    float v = x[tid];
    float sq = v * v;
    #pragma unroll
    for (int o = 16; o > 0; o >>= 1) sq += __shfl_xor_sync(0xffffffffu, sq, o);
    __shared__ float ws[4];
    if ((tid & 31) == 0) ws[tid >> 5] = sq;
    __syncthreads();
    float total = ws[0] + ws[1] + ws[2] + ws[3];
    float rinv = rsqrtf(total * (1.0f / HDIM) + EPSV);

    __shared__ float xn[HDIM];
    xn[tid] = v * rinv * gamma[tid];
    __syncthreads();

    if (tid < 64) {
        float c = cosT[(size_t)s * 64 + tid];
        float sn = sinT[(size_t)s * 64 + tid];
        float x1 = xn[tid];
        float x2 = xn[tid + 64];
        float y1 = x1 * c - x2 * sn;
        float y2 = x2 * c + x1 * sn;
        __nv_bfloat16 h1 = __float2bfloat16(y1);
        __nv_bfloat16 h2 = __float2bfloat16(y2);
        dh[tid] = h1;
        dh[tid + 64] = h2;
        dl[tid] = __float2bfloat16(y1 - __bfloat162float(h1));
        dl[tid + 64] = __float2bfloat16(y2 - __bfloat162float(h2));
    }
}

// ---------------------------------------------------------------------------
// V: fp32 [seq][kvh*128 cols] -> transposed fp16 hi/lo [kvh][d][seq]
// ---------------------------------------------------------------------------
__global__ __launch_bounds__(256) void v_split_transpose(
    __half* __restrict__ TH, __half* __restrict__ TL)
{
    __shared__ float t[32][33];
    const int t0 = blockIdx.x * 32;
    const int d0 = blockIdx.y * 32;
    const int kh = blockIdx.z;
    const int tx = threadIdx.x & 31, ty = threadIdx.x >> 5;
    #pragma unroll
    for (int i = 0; i < 4; i++)
        t[ty + 8 * i][tx] =
            g_qkv[(size_t)(t0 + ty + 8 * i) * QKVN + (NQH + NKVH) * HDIM + kh * HDIM + d0 + tx];
    __syncthreads();
    #pragma unroll
    for (int i = 0; i < 4; i++) {
        float x = t[tx][ty + 8 * i];
        __half h = __float2half_rn(x);
        size_t o = ((size_t)kh * HDIM + d0 + ty + 8 * i) * SLEN + t0 + tx;
        TH[o] = h;
        TL[o] = __float2half_rn(x - __half2float(h));
    }
}

// ---------------------------------------------------------------------------
// fp32 -> fp16 hi/lo split (elementwise)
// ---------------------------------------------------------------------------
__global__ void split_rows_kernel(const float* __restrict__ X,
                                  __half* __restrict__ H,
                                  __half* __restrict__ L, int n)
{
    int i = blockIdx.x * blockDim.x + threadIdx.x;
    if (i < n) {
        float x = X[i];
        __half h = __float2half_rn(x);
        H[i] = h;
        L[i] = __float2half_rn(x - __half2float(h));
    }
}

// fp32 [K,N] -> transposed fp16 hi [N,K] (weights: hi only)
__global__ __launch_bounds__(256) void split_transpose_kernel(
    const float* __restrict__ W, __half* __restrict__ TH, int K, int N)
{
    __shared__ float t[32][33];
    const int n0 = blockIdx.x * 32, k0 = blockIdx.y * 32;
    const int tx = threadIdx.x & 31, ty = threadIdx.x >> 5;
    #pragma unroll
    for (int i = 0; i < 4; i++)
        t[ty + 8 * i][tx] = W[(size_t)(k0 + ty + 8 * i) * N + n0 + tx];
    __syncthreads();
    #pragma unroll
    for (int i = 0; i < 4; i++) {
        float x = t[tx][ty + 8 * i];
        size_t o = (size_t)(n0 + ty + 8 * i) * K + k0 + tx;
        TH[o] = __float2half_rn(x);
    }
}

// ---------------------------------------------------------------------------
// launch
// ---------------------------------------------------------------------------
extern "C" void kernel_launch(void* const* d_in, const int* in_sizes, int n_in,
                              void* d_out, int out_size)
{
    (void)in_sizes; (void)n_in; (void)out_size;
    const float* hidden = (const float*)d_in[1];
    const float* Wqkv   = (const float*)d_in[2];
    const float* Wo     = (const float*)d_in[3];
    const float* qg     = (const float*)d_in[4];
    const float* kg     = (const float*)d_in[5];
    const float* cosT   = (const float*)d_in[6];
    const float* sinT   = (const float*)d_in[7];
    float* out = (float*)d_out;

    float* qkv;
    __half *wT_hi, *a_hi, *a_lo, *vt_hi, *vt_lo;
    __nv_bfloat16 *q_hi, *q_lo, *k_hi, *k_lo;
    cudaGetSymbolAddress((void**)&qkv, g_qkv);
    cudaGetSymbolAddress((void**)&wT_hi, g_wT_hi);
    cudaGetSymbolAddress((void**)&a_hi, g_a_hi);
    cudaGetSymbolAddress((void**)&a_lo, g_a_lo);
    cudaGetSymbolAddress((void**)&q_hi, g_q_hi);
    cudaGetSymbolAddress((void**)&q_lo, g_q_lo);
    cudaGetSymbolAddress((void**)&k_hi, g_k_hi);
    cudaGetSymbolAddress((void**)&k_lo, g_k_lo);
    cudaGetSymbolAddress((void**)&vt_hi, g_vt_hi);
    cudaGetSymbolAddress((void**)&vt_lo, g_vt_lo);

    cudaFuncSetAttribute(gemm_fp16x2, cudaFuncAttributeMaxDynamicSharedMemorySize, MM_SMEM_TOT);
    cudaFuncSetAttribute(flash_attn, cudaFuncAttributeMaxDynamicSharedMemorySize, FA_SMEM);

    // 1) QKV projection (fp16x2: A hi+lo, W hi)
    split_transpose_kernel<<<dim3(QKVN / 32, HID / 32), 256>>>(Wqkv, wT_hi, HID, QKVN);
    split_rows_kernel<<<(SLEN * HID + 255) / 256, 256>>>(hidden, a_hi, a_lo, SLEN * HID);
    gemm_fp16x2<<<dim3(QKVN / 128, SLEN / 128), 256, MM_SMEM_TOT>>>(
        a_hi, a_lo, wT_hi, qkv, HID, QKVN);

    // 2) RMSNorm + RoPE -> bf16 hi/lo Q, K ; V transpose+split (fp16)
    rmsnorm_rope_split<<<dim3(SLEN, NQH + NKVH), 128>>>(cosT, sinT, qg, kg,
                                                        q_hi, q_lo, k_hi, k_lo);
    v_split_transpose<<<dim3(SLEN / 32, HDIM / 32, NKVH), 256>>>(vt_hi, vt_lo);

    // 3) Fused flash attention -> a_hi/a_lo (fp16, O-proj input)
    flash_attn<<<dim3(NQB, NQH), 256, FA_SMEM>>>(
        q_hi, q_lo, k_hi, k_lo, vt_hi, vt_lo, a_hi, a_lo);

    // 4) Output projection (fp16x2)
    split_transpose_kernel<<<dim3(HID / 32, HID / 32), 256>>>(Wo, wT_hi, HID, HID);
    gemm_fp16x2<<<dim3(HID / 128, SLEN / 128), 256, MM_SMEM_TOT>>>(
        a_hi, a_lo, wT_hi, out, HID, HID);
}